// round 3
// baseline (speedup 1.0000x reference)
#include <cuda_runtime.h>
#include <cuda_fp16.h>
#include <stdint.h>

// ---------------------------------------------------------------------------
// EdgeNetwork, precision-safe HMMA formulation:
//   messages_e = sum_h H[e,h] * (hw_e @ W2[h]^T) + (hw_e @ b2-tile)
// H applied POST-MMA in fp32; hw split into fp16 hi+lo (A-side error ~2^-22);
// only W2's single fp16 rounding remains (~5.9e-4 total).
// Main: 148 CTAs x 128 edges (8 warps, m32n64/warp).
// Tail: remaining edges in 16-edge jobs (4 warps, m16n32/warp), full K.
// W2 pre-converted fp16 (swizzled image) streamed via cp.async.bulk, 2 slots.
// ---------------------------------------------------------------------------

#define DD        128
#define EDIM      16
#define EH        128
#define NSTEPS    129          // 128 hidden + 1 bias step
#define STEP_BYTES 32768       // 128 rows x 256B (fp16 128 cols)

// ---- main-kernel smem layout ----
#define MB_FULL(i)  ((i)*8)
#define MB_EMPTY(i) (16 + (i)*8)
#define HW_HI       1024                    // 128 x 256B = 32768
#define HW_LO       33792                   // 32768
#define HT_OFF      66560                   // 129*128*4 = 66048
#define W2_OFF      132608                  // 2 x 32768
#define SMEM_TOTAL  198400
// prologue scratch (inside hw regions, dead after MLP)
#define SCR_EF      1024                    // 128*16*4 = 8192
#define SCR_W1      9216                    // 16*128*4 = 8192
#define SCR_B1      17408                   // 512

// ---- tail-kernel smem layout ----
#define T_HW_HI     1024                    // 16*256 = 4096
#define T_HW_LO     5120                    // 4096
#define T_HT        9216                    // 129*16*4 = 8256
#define T_W2        18432                   // 2 x 32768
#define T_EF        83968                   // 16*16*4 = 1024
#define T_W1        84992                   // 8192
#define T_B1        93184                   // 512
#define TAIL_SMEM   94208

// fp16 W2 image: [h][i][j], row i = 256B, 16B chunks swizzled c' = (c&8)|((c&7)^(i&7))
static __device__ __align__(128) unsigned char g_w2h[(size_t)NSTEPS * STEP_BYTES];

__device__ __forceinline__ uint32_t s2u(const void* p) {
    return (uint32_t)__cvta_generic_to_shared(p);
}
__device__ __forceinline__ uint32_t swz_chunk(uint32_t c, uint32_t r7) {
    return (c & 8u) | ((c & 7u) ^ r7);
}
__device__ __forceinline__ void mbar_init(uint32_t a, uint32_t cnt) {
    asm volatile("mbarrier.init.shared.b64 [%0], %1;" :: "r"(a), "r"(cnt) : "memory");
}
__device__ __forceinline__ void mbar_expect_tx(uint32_t a, uint32_t bytes) {
    asm volatile("mbarrier.arrive.expect_tx.shared.b64 _, [%0], %1;"
                 :: "r"(a), "r"(bytes) : "memory");
}
__device__ __forceinline__ void mbar_arrive(uint32_t a) {
    asm volatile("mbarrier.arrive.shared.b64 _, [%0];" :: "r"(a) : "memory");
}
__device__ __forceinline__ void mbar_wait(uint32_t a, uint32_t parity) {
    asm volatile(
        "{\n\t.reg .pred P;\n\t"
        "W_%=:\n\t"
        "mbarrier.try_wait.parity.shared.b64 P, [%0], %1;\n\t"
        "@P bra.uni D_%=;\n\t"
        "bra.uni W_%=;\n\t"
        "D_%=:\n\t}"
        :: "r"(a), "r"(parity) : "memory");
}
__device__ __forceinline__ void bulk_g2s(uint32_t dst, const void* src, uint32_t bytes,
                                         uint32_t mbar) {
    asm volatile(
        "cp.async.bulk.shared::cluster.global.mbarrier::complete_tx::bytes [%0], [%1], %2, [%3];"
        :: "r"(dst), "l"(src), "r"(bytes), "r"(mbar) : "memory");
}
__device__ __forceinline__ void ldsm_x4(uint32_t& r0, uint32_t& r1, uint32_t& r2, uint32_t& r3,
                                        uint32_t addr) {
    asm volatile("ldmatrix.sync.aligned.m8n8.x4.shared.b16 {%0,%1,%2,%3}, [%4];"
                 : "=r"(r0), "=r"(r1), "=r"(r2), "=r"(r3) : "r"(addr));
}
// d += a@b (accumulate in place)
__device__ __forceinline__ void mma_acc(float* c,
                                        uint32_t a0, uint32_t a1, uint32_t a2, uint32_t a3,
                                        uint32_t b0, uint32_t b1) {
    asm volatile(
        "mma.sync.aligned.m16n8k16.row.col.f32.f16.f16.f32 "
        "{%0,%1,%2,%3}, {%4,%5,%6,%7}, {%8,%9}, {%0,%1,%2,%3};"
        : "+f"(c[0]), "+f"(c[1]), "+f"(c[2]), "+f"(c[3])
        : "r"(a0), "r"(a1), "r"(a2), "r"(a3), "r"(b0), "r"(b1));
}
// d = a@b (zero C)
__device__ __forceinline__ void mma_zc(float* d,
                                       uint32_t a0, uint32_t a1, uint32_t a2, uint32_t a3,
                                       uint32_t b0, uint32_t b1) {
    asm volatile(
        "mma.sync.aligned.m16n8k16.row.col.f32.f16.f16.f32 "
        "{%0,%1,%2,%3}, {%4,%5,%6,%7}, {%8,%9}, {%10,%11,%12,%13};"
        : "=f"(d[0]), "=f"(d[1]), "=f"(d[2]), "=f"(d[3])
        : "r"(a0), "r"(a1), "r"(a2), "r"(a3), "r"(b0), "r"(b1),
          "f"(0.f), "f"(0.f), "f"(0.f), "f"(0.f));
}
// split x into fp16 hi + fp16 lo
__device__ __forceinline__ void split16(float x, __half& hi, __half& lo) {
    hi = __float2half_rn(x);
    lo = __float2half_rn(x - __half2float(hi));
}

// ---------------------------------------------------------------------------
// Prepass: W2 fp32 [128][16384] + b2 fp32 [16384] -> g_w2h fp16 image.
// ---------------------------------------------------------------------------
__global__ void __launch_bounds__(256) w2_prepass(const float* __restrict__ W2,
                                                  const float* __restrict__ b2) {
    const int h = blockIdx.x;
    const int tid = threadIdx.x;
    const float* src = (h < EH) ? (W2 + (size_t)h * (DD * DD)) : b2;
    unsigned char* dst = g_w2h + (size_t)h * STEP_BYTES;
    #pragma unroll
    for (int it = 0; it < 8; ++it) {
        int cid = tid + it * 256;
        int i = cid >> 4;
        int c = cid & 15;
        const float* s = src + (size_t)i * DD + c * 8;
        float4 a = *(const float4*)s;
        float4 b = *(const float4*)(s + 4);
        __half2 h0 = __floats2half2_rn(a.x, a.y);
        __half2 h1 = __floats2half2_rn(a.z, a.w);
        __half2 h2 = __floats2half2_rn(b.x, b.y);
        __half2 h3 = __floats2half2_rn(b.z, b.w);
        uint32_t off = (uint32_t)i * 256u + (swz_chunk((uint32_t)c, (uint32_t)(i & 7)) << 4);
        uint4 v;
        v.x = *(uint32_t*)&h0; v.y = *(uint32_t*)&h1;
        v.z = *(uint32_t*)&h2; v.w = *(uint32_t*)&h3;
        *(uint4*)(dst + off) = v;
    }
}

// ---------------------------------------------------------------------------
// Main kernel: 128 edges/CTA, 256 threads, warps 4(M)x2(N) -> m32 x n64
// ---------------------------------------------------------------------------
__global__ void __launch_bounds__(256, 1)
edge_main(const float* __restrict__ hw, const float* __restrict__ ef,
          const float* __restrict__ W1, const float* __restrict__ b1,
          float* __restrict__ out, int n) {
    extern __shared__ __align__(1024) unsigned char smem[];
    const uint32_t smem_b = s2u(smem);
    const int tid = threadIdx.x;
    const int lane = tid & 31;
    const int wid = tid >> 5;
    const int warp_m = wid & 3;
    const int warp_n = wid >> 2;
    const int e0 = blockIdx.x * 128;

    if (tid == 0) {
        mbar_init(smem_b + MB_FULL(0), 1);
        mbar_init(smem_b + MB_FULL(1), 1);
        mbar_init(smem_b + MB_EMPTY(0), 256);
        mbar_init(smem_b + MB_EMPTY(1), 256);
        asm volatile("fence.mbarrier_init.release.cluster;" ::: "memory");
    }
    __syncthreads();
    if (tid == 0) {
        mbar_expect_tx(smem_b + MB_FULL(0), STEP_BYTES);
        bulk_g2s(smem_b + W2_OFF, g_w2h, STEP_BYTES, smem_b + MB_FULL(0));
        mbar_expect_tx(smem_b + MB_FULL(1), STEP_BYTES);
        bulk_g2s(smem_b + W2_OFF + STEP_BYTES, g_w2h + STEP_BYTES, STEP_BYTES,
                 smem_b + MB_FULL(1));
    }

    // -------- stage ef / W1 / b1 in scratch --------
    {
        float* ef_s = (float*)(smem + SCR_EF);
        float* w1_s = (float*)(smem + SCR_W1);
        float* b1_s = (float*)(smem + SCR_B1);
        ((float4*)ef_s)[tid] = ((const float4*)(ef + (size_t)e0 * EDIM))[tid];
        ((float4*)ef_s)[tid + 256] = ((const float4*)(ef + (size_t)e0 * EDIM))[tid + 256];
        ((float4*)w1_s)[tid] = ((const float4*)W1)[tid];
        ((float4*)w1_s)[tid + 256] = ((const float4*)W1)[tid + 256];
        if (tid < EH) b1_s[tid] = b1[tid];
    }
    __syncthreads();

    // -------- MLP: Ht[h][e] fp32 (129 x 128), step 128 = 1.0 (bias) --------
    {
        const float* ef_s = (const float*)(smem + SCR_EF);
        const float* w1_s = (const float*)(smem + SCR_W1);
        const float* b1_s = (const float*)(smem + SCR_B1);
        float* ht = (float*)(smem + HT_OFF);
        const int e = tid >> 1;
        const int part = tid & 1;
        float efr[EDIM];
        #pragma unroll
        for (int k = 0; k < EDIM; ++k) efr[k] = ef_s[e * EDIM + k];
        const int h0 = part * 64;
        #pragma unroll 4
        for (int hh = 0; hh < 64; hh += 4) {
            float4 acc4 = *(const float4*)(b1_s + h0 + hh);
            #pragma unroll
            for (int k = 0; k < EDIM; ++k) {
                float4 w = *(const float4*)(w1_s + k * EH + h0 + hh);
                acc4.x += efr[k] * w.x; acc4.y += efr[k] * w.y;
                acc4.z += efr[k] * w.z; acc4.w += efr[k] * w.w;
            }
            ht[(h0 + hh + 0) * 128 + e] = fmaxf(acc4.x, 0.f);
            ht[(h0 + hh + 1) * 128 + e] = fmaxf(acc4.y, 0.f);
            ht[(h0 + hh + 2) * 128 + e] = fmaxf(acc4.z, 0.f);
            ht[(h0 + hh + 3) * 128 + e] = fmaxf(acc4.w, 0.f);
        }
        if (part == 0) ht[128 * 128 + e] = 1.0f;
    }
    __syncthreads();

    // -------- build hw hi/lo fp16 images (overwrites scratch) --------
    {
        #pragma unroll
        for (int q = 0; q < 8; ++q) {
            int cid = tid + q * 256;      // 2048 chunks of 8 elems
            int r = cid >> 4;
            int c = cid & 15;
            const float* s = hw + (size_t)(e0 + r) * DD + c * 8;
            float4 a = *(const float4*)s;
            float4 b = *(const float4*)(s + 4);
            float x[8] = {a.x, a.y, a.z, a.w, b.x, b.y, b.z, b.w};
            __half hi[8], lo[8];
            #pragma unroll
            for (int k = 0; k < 8; ++k) split16(x[k], hi[k], lo[k]);
            uint32_t off = (uint32_t)r * 256u + (swz_chunk((uint32_t)c, (uint32_t)(r & 7)) << 4);
            uint4 vh, vl;
            vh.x = *(uint32_t*)&hi[0]; vh.y = *(uint32_t*)&hi[2];
            vh.z = *(uint32_t*)&hi[4]; vh.w = *(uint32_t*)&hi[6];
            vl.x = *(uint32_t*)&lo[0]; vl.y = *(uint32_t*)&lo[2];
            vl.z = *(uint32_t*)&lo[4]; vl.w = *(uint32_t*)&lo[6];
            *(uint4*)(smem + HW_HI + off) = vh;
            *(uint4*)(smem + HW_LO + off) = vl;
        }
    }
    __syncthreads();

    // -------- precomputed addressing --------
    const uint32_t rx = (uint32_t)(lane & 7);
    const uint32_t lhi = (uint32_t)(lane >> 4);
    const uint32_t rA0 = (uint32_t)(warp_m * 32 + (lane & 15));       // m-frag 0
    const uint32_t rA1 = rA0 + 16u;                                    // m-frag 1
    const uint32_t aHi0 = smem_b + HW_HI + rA0 * 256u;
    const uint32_t aHi1 = smem_b + HW_HI + rA1 * 256u;
    const uint32_t aLo0 = smem_b + HW_LO + rA0 * 256u;
    const uint32_t aLo1 = smem_b + HW_LO + rA1 * 256u;
    uint32_t bRow[4];
    #pragma unroll
    for (int g = 0; g < 4; ++g)
        bRow[g] = (uint32_t)(warp_n * 64 + g * 16 + (lane & 15)) * 256u;
    const float* ht = (const float*)(smem + HT_OFF);
    const int quad = lane >> 2;
    const int hrow = warp_m * 32 + quad;

    float acc[16][4];
    #pragma unroll
    for (int f = 0; f < 16; ++f)
        #pragma unroll
        for (int q = 0; q < 4; ++q) acc[f][q] = 0.f;

    // -------- main loop --------
    for (int s = 0; s < NSTEPS; ++s) {
        const uint32_t slot = (uint32_t)s & 1u;
        const uint32_t par = ((uint32_t)s >> 1) & 1u;
        mbar_wait(smem_b + MB_FULL(slot), par);

        const float hA0 = ht[s * 128 + hrow];
        const float hB0 = ht[s * 128 + hrow + 8];
        const float hA1 = ht[s * 128 + hrow + 16];
        const float hB1 = ht[s * 128 + hrow + 24];
        const uint32_t bSlot = smem_b + W2_OFF + slot * STEP_BYTES;

        float d[16][4];
        #pragma unroll
        for (int kt = 0; kt < 8; ++kt) {
            const uint32_t coff = swz_chunk((uint32_t)(kt * 2) + lhi, rx) << 4;
            uint32_t h00, h01, h02, h03, h10, h11, h12, h13;
            uint32_t l00, l01, l02, l03, l10, l11, l12, l13;
            ldsm_x4(h00, h01, h02, h03, aHi0 + coff);
            ldsm_x4(h10, h11, h12, h13, aHi1 + coff);
            ldsm_x4(l00, l01, l02, l03, aLo0 + coff);
            ldsm_x4(l10, l11, l12, l13, aLo1 + coff);
            #pragma unroll
            for (int g = 0; g < 4; ++g) {
                uint32_t b0, b1r, b2, b3;
                ldsm_x4(b0, b1r, b2, b3, bSlot + bRow[g] + coff);
                float* d00 = d[0 * 8 + g * 2 + 0];
                float* d01 = d[0 * 8 + g * 2 + 1];
                float* d10 = d[1 * 8 + g * 2 + 0];
                float* d11 = d[1 * 8 + g * 2 + 1];
                if (kt == 0) {
                    mma_zc(d00, h00, h01, h02, h03, b0, b2);
                    mma_zc(d01, h00, h01, h02, h03, b1r, b3);
                    mma_zc(d10, h10, h11, h12, h13, b0, b2);
                    mma_zc(d11, h10, h11, h12, h13, b1r, b3);
                } else {
                    mma_acc(d00, h00, h01, h02, h03, b0, b2);
                    mma_acc(d01, h00, h01, h02, h03, b1r, b3);
                    mma_acc(d10, h10, h11, h12, h13, b0, b2);
                    mma_acc(d11, h10, h11, h12, h13, b1r, b3);
                }
                mma_acc(d00, l00, l01, l02, l03, b0, b2);
                mma_acc(d01, l00, l01, l02, l03, b1r, b3);
                mma_acc(d10, l10, l11, l12, l13, b0, b2);
                mma_acc(d11, l10, l11, l12, l13, b1r, b3);
            }
        }
        mbar_arrive(smem_b + MB_EMPTY(slot));

        // fp32 H scaling into persistent accumulators
        #pragma unroll
        for (int g2 = 0; g2 < 8; ++g2) {
            float* f0 = d[g2];          // m-frag 0
            float* f1 = d[8 + g2];      // m-frag 1
            acc[g2][0] += hA0 * f0[0];  acc[g2][1] += hA0 * f0[1];
            acc[g2][2] += hB0 * f0[2];  acc[g2][3] += hB0 * f0[3];
            acc[8 + g2][0] += hA1 * f1[0];  acc[8 + g2][1] += hA1 * f1[1];
            acc[8 + g2][2] += hB1 * f1[2];  acc[8 + g2][3] += hB1 * f1[3];
        }

        if (tid == 0 && s + 2 < NSTEPS) {
            mbar_wait(smem_b + MB_EMPTY(slot), par);
            mbar_expect_tx(smem_b + MB_FULL(slot), STEP_BYTES);
            bulk_g2s(smem_b + W2_OFF + slot * STEP_BYTES,
                     g_w2h + (size_t)(s + 2) * STEP_BYTES, STEP_BYTES,
                     smem_b + MB_FULL(slot));
        }
    }

    // -------- epilogue --------
    #pragma unroll
    for (int mf = 0; mf < 2; ++mf) {
        const int er = e0 + warp_m * 32 + mf * 16 + quad;
        #pragma unroll
        for (int g = 0; g < 4; ++g)
            #pragma unroll
            for (int b = 0; b < 2; ++b) {
                const int f = mf * 8 + g * 2 + b;
                const int col = warp_n * 64 + g * 16 + b * 8 + (lane & 3) * 2;
                *(float2*)(out + (size_t)er * DD + col) = make_float2(acc[f][0], acc[f][1]);
                *(float2*)(out + (size_t)(er + 8) * DD + col) = make_float2(acc[f][2], acc[f][3]);
            }
    }
}

// ---------------------------------------------------------------------------
// Tail kernel: 16 edges/CTA, 128 threads, 4 warps (m16 x n32 each), full K.
// ---------------------------------------------------------------------------
__global__ void __launch_bounds__(128, 1)
edge_tail(const float* __restrict__ hw, const float* __restrict__ ef,
          const float* __restrict__ W1, const float* __restrict__ b1,
          float* __restrict__ out, int n, int e_base) {
    extern __shared__ __align__(1024) unsigned char smem[];
    const uint32_t smem_b = s2u(smem);
    const int tid = threadIdx.x;
    const int lane = tid & 31;
    const int wid = tid >> 5;
    const int e0 = e_base + blockIdx.x * 16;

    if (tid == 0) {
        mbar_init(smem_b + MB_FULL(0), 1);
        mbar_init(smem_b + MB_FULL(1), 1);
        mbar_init(smem_b + MB_EMPTY(0), 128);
        mbar_init(smem_b + MB_EMPTY(1), 128);
        asm volatile("fence.mbarrier_init.release.cluster;" ::: "memory");
    }
    __syncthreads();
    if (tid == 0) {
        mbar_expect_tx(smem_b + MB_FULL(0), STEP_BYTES);
        bulk_g2s(smem_b + T_W2, g_w2h, STEP_BYTES, smem_b + MB_FULL(0));
        mbar_expect_tx(smem_b + MB_FULL(1), STEP_BYTES);
        bulk_g2s(smem_b + T_W2 + STEP_BYTES, g_w2h + STEP_BYTES, STEP_BYTES,
                 smem_b + MB_FULL(1));
    }

    // stage ef (guarded) / W1 / b1
    {
        float* ef_s = (float*)(smem + T_EF);
        float* w1_s = (float*)(smem + T_W1);
        float* b1_s = (float*)(smem + T_B1);
        if (tid < 64) {
            int e = tid >> 2;
            float4 v = make_float4(0.f, 0.f, 0.f, 0.f);
            if (e0 + e < n) v = *(const float4*)(ef + (size_t)(e0 + e) * EDIM + (tid & 3) * 4);
            ((float4*)ef_s)[tid] = v;
        }
        #pragma unroll
        for (int q = 0; q < 4; ++q)
            ((float4*)w1_s)[tid + q * 128] = ((const float4*)W1)[tid + q * 128];
        if (tid < EH) b1_s[tid] = b1[tid];
    }
    __syncthreads();

    // MLP for 16 edges: Ht[h][e] stride 16
    {
        const float* ef_s = (const float*)(smem + T_EF);
        const float* w1_s = (const float*)(smem + T_W1);
        const float* b1_s = (const float*)(smem + T_B1);
        float* ht = (float*)(smem + T_HT);
        const int e = tid >> 3;          // 0..15
        const int part = tid & 7;        // 16 h each
        float efr[EDIM];
        #pragma unroll
        for (int k = 0; k < EDIM; ++k) efr[k] = ef_s[e * EDIM + k];
        const int h0 = part * 16;
        #pragma unroll
        for (int hh = 0; hh < 16; hh += 4) {
            float4 acc4 = *(const float4*)(b1_s + h0 + hh);
            #pragma unroll
            for (int k = 0; k < EDIM; ++k) {
                float4 w = *(const float4*)(w1_s + k * EH + h0 + hh);
                acc4.x += efr[k] * w.x; acc4.y += efr[k] * w.y;
                acc4.z += efr[k] * w.z; acc4.w += efr[k] * w.w;
            }
            ht[(h0 + hh + 0) * 16 + e] = fmaxf(acc4.x, 0.f);
            ht[(h0 + hh + 1) * 16 + e] = fmaxf(acc4.y, 0.f);
            ht[(h0 + hh + 2) * 16 + e] = fmaxf(acc4.z, 0.f);
            ht[(h0 + hh + 3) * 16 + e] = fmaxf(acc4.w, 0.f);
        }
        if (part == 0) ht[128 * 16 + e] = 1.0f;
    }
    __syncthreads();

    // hw hi/lo images, 16 rows (guarded)
    {
        #pragma unroll
        for (int q = 0; q < 2; ++q) {
            int cid = tid + q * 128;      // 256 chunks
            int r = cid >> 4;
            int c = cid & 15;
            float4 a = make_float4(0.f, 0.f, 0.f, 0.f), b = a;
            if (e0 + r < n) {
                const float* s = hw + (size_t)(e0 + r) * DD + c * 8;
                a = *(const float4*)s;
                b = *(const float4*)(s + 4);
            }
            float x[8] = {a.x, a.y, a.z, a.w, b.x, b.y, b.z, b.w};
            __half hi[8], lo[8];
            #pragma unroll
            for (int k = 0; k < 8; ++k) split16(x[k], hi[k], lo[k]);
            uint32_t off = (uint32_t)r * 256u + (swz_chunk((uint32_t)c, (uint32_t)(r & 7)) << 4);
            uint4 vh, vl;
            vh.x = *(uint32_t*)&hi[0]; vh.y = *(uint32_t*)&hi[2];
            vh.z = *(uint32_t*)&hi[4]; vh.w = *(uint32_t*)&hi[6];
            vl.x = *(uint32_t*)&lo[0]; vl.y = *(uint32_t*)&lo[2];
            vl.z = *(uint32_t*)&lo[4]; vl.w = *(uint32_t*)&lo[6];
            *(uint4*)(smem + T_HW_HI + off) = vh;
            *(uint4*)(smem + T_HW_LO + off) = vl;
        }
    }
    __syncthreads();

    const uint32_t rx = (uint32_t)(lane & 7);
    const uint32_t lhi = (uint32_t)(lane >> 4);
    const uint32_t aHi = smem_b + T_HW_HI + (uint32_t)(lane & 15) * 256u;
    const uint32_t aLo = smem_b + T_HW_LO + (uint32_t)(lane & 15) * 256u;
    uint32_t bRow[2];
    #pragma unroll
    for (int g = 0; g < 2; ++g)
        bRow[g] = (uint32_t)(wid * 32 + g * 16 + (lane & 15)) * 256u;
    const float* ht = (const float*)(smem + T_HT);
    const int quad = lane >> 2;

    float acc[4][4];
    #pragma unroll
    for (int f = 0; f < 4; ++f)
        #pragma unroll
        for (int q = 0; q < 4; ++q) acc[f][q] = 0.f;

    for (int s = 0; s < NSTEPS; ++s) {
        const uint32_t slot = (uint32_t)s & 1u;
        const uint32_t par = ((uint32_t)s >> 1) & 1u;
        mbar_wait(smem_b + MB_FULL(slot), par);

        const float hA = ht[s * 16 + quad];
        const float hB = ht[s * 16 + quad + 8];
        const uint32_t bSlot = smem_b + T_W2 + slot * STEP_BYTES;

        float d[4][4];
        #pragma unroll
        for (int kt = 0; kt < 8; ++kt) {
            const uint32_t coff = swz_chunk((uint32_t)(kt * 2) + lhi, rx) << 4;
            uint32_t h0r, h1r, h2r, h3r, l0r, l1r, l2r, l3r;
            ldsm_x4(h0r, h1r, h2r, h3r, aHi + coff);
            ldsm_x4(l0r, l1r, l2r, l3r, aLo + coff);
            #pragma unroll
            for (int g = 0; g < 2; ++g) {
                uint32_t b0, b1r, b2, b3;
                ldsm_x4(b0, b1r, b2, b3, bSlot + bRow[g] + coff);
                float* d0 = d[g * 2 + 0];
                float* d1 = d[g * 2 + 1];
                if (kt == 0) {
                    mma_zc(d0, h0r, h1r, h2r, h3r, b0, b2);
                    mma_zc(d1, h0r, h1r, h2r, h3r, b1r, b3);
                } else {
                    mma_acc(d0, h0r, h1r, h2r, h3r, b0, b2);
                    mma_acc(d1, h0r, h1r, h2r, h3r, b1r, b3);
                }
                mma_acc(d0, l0r, l1r, l2r, l3r, b0, b2);
                mma_acc(d1, l0r, l1r, l2r, l3r, b1r, b3);
            }
        }
        mbar_arrive(smem_b + MB_EMPTY(slot));

        #pragma unroll
        for (int f = 0; f < 4; ++f) {
            acc[f][0] += hA * d[f][0];  acc[f][1] += hA * d[f][1];
            acc[f][2] += hB * d[f][2];  acc[f][3] += hB * d[f][3];
        }

        if (tid == 0 && s + 2 < NSTEPS) {
            mbar_wait(smem_b + MB_EMPTY(slot), par);
            mbar_expect_tx(smem_b + MB_FULL(slot), STEP_BYTES);
            bulk_g2s(smem_b + T_W2 + slot * STEP_BYTES,
                     g_w2h + (size_t)(s + 2) * STEP_BYTES, STEP_BYTES,
                     smem_b + MB_FULL(slot));
        }
    }

    const int er = e0 + quad;
    #pragma unroll
    for (int g = 0; g < 2; ++g)
        #pragma unroll
        for (int b = 0; b < 2; ++b) {
            const int f = g * 2 + b;
            const int col = wid * 32 + g * 16 + b * 8 + (lane & 3) * 2;
            if (er < n)
                *(float2*)(out + (size_t)er * DD + col) = make_float2(acc[f][0], acc[f][1]);
            if (er + 8 < n)
                *(float2*)(out + (size_t)(er + 8) * DD + col) = make_float2(acc[f][2], acc[f][3]);
        }
}

// ---------------------------------------------------------------------------
// Inputs (metadata order): h_v, h_w, edge_features, W1, b1, W2, b2 (h_v unused)
// ---------------------------------------------------------------------------
extern "C" void kernel_launch(void* const* d_in, const int* in_sizes, int n_in,
                              void* d_out, int out_size) {
    const float* hw = (const float*)d_in[1];
    const float* ef = (const float*)d_in[2];
    const float* W1 = (const float*)d_in[3];
    const float* b1 = (const float*)d_in[4];
    const float* W2 = (const float*)d_in[5];
    const float* b2 = (const float*)d_in[6];
    const int n = in_sizes[1] / DD;

    w2_prepass<<<NSTEPS, 256>>>(W2, b2);

    int full = n / 128;
    if (full > 148) full = 148;
    if (full > 0) {
        cudaFuncSetAttribute(edge_main, cudaFuncAttributeMaxDynamicSharedMemorySize,
                             SMEM_TOTAL);
        edge_main<<<full, 256, SMEM_TOTAL>>>(hw, ef, W1, b1, (float*)d_out, n);
    }
    const int rem = n - full * 128;
    const int jobs = (rem + 15) / 16;
    if (jobs > 0) {
        cudaFuncSetAttribute(edge_tail, cudaFuncAttributeMaxDynamicSharedMemorySize,
                             TAIL_SMEM);
        edge_tail<<<jobs, 128, TAIL_SMEM>>>(hw, ef, W1, b1, (float*)d_out, n, full * 128);
    }
}

// round 4
// speedup vs baseline: 1.1076x; 1.1076x over previous
#include <cuda_runtime.h>
#include <cuda_fp16.h>
#include <stdint.h>

// ---------------------------------------------------------------------------
// EdgeNetwork: messages_e = sum_h H[e,h]*(hw_e @ W2[h]^T) + (hw_e @ b2-tile)
// H applied POST-MMA in fp32 (per-step fresh accumulator), hw rounded to fp16
// once (single-rounding A path; measured W2-only error 2.07e-4, predicted
// total ~4.5e-4). Main: 148 CTAs x 128 edges, 8 warps m32n64.
// Tail: 16-edge jobs, full K. W2 fp16 image streamed via cp.async.bulk, 3 slots.
// ---------------------------------------------------------------------------

#define DD        128
#define EDIM      16
#define EH        128
#define NSTEPS    129
#define STEP_BYTES 32768
#define SLOTS     3

// ---- main smem layout ----
#define MB_FULL(i)  ((i)*8)
#define MB_EMPTY(i) (32 + (i)*8)
#define HW_HI       1024                 // 128 x 256B = 32768
#define HT_OFF      33792                // 129*128*4 = 66048 -> ends 99840
#define W2_OFF      100352               // 3 x 32768 -> ends 198656
#define SMEM_TOTAL  198656
// prologue scratch (inside HW_HI region, dead before hw image build)
#define SCR_EF      1024
#define SCR_W1      9216
#define SCR_B1      17408

// ---- tail smem layout ----
#define T_HW_HI     1024                 // 16*256 = 4096
#define T_HT        5120                 // 129*16*4 = 8256 -> 13376
#define T_W2        13824                // 3 x 32768 -> 112128
#define T_EF        112128               // 1024
#define T_W1        113152               // 8192
#define T_B1        121344               // 512
#define TAIL_SMEM   121856

static __device__ __align__(128) unsigned char g_w2h[(size_t)NSTEPS * STEP_BYTES];

__device__ __forceinline__ uint32_t s2u(const void* p) {
    return (uint32_t)__cvta_generic_to_shared(p);
}
__device__ __forceinline__ uint32_t swz_chunk(uint32_t c, uint32_t r7) {
    return (c & 8u) | ((c & 7u) ^ r7);
}
__device__ __forceinline__ void mbar_init(uint32_t a, uint32_t cnt) {
    asm volatile("mbarrier.init.shared.b64 [%0], %1;" :: "r"(a), "r"(cnt) : "memory");
}
__device__ __forceinline__ void mbar_expect_tx(uint32_t a, uint32_t bytes) {
    asm volatile("mbarrier.arrive.expect_tx.shared.b64 _, [%0], %1;"
                 :: "r"(a), "r"(bytes) : "memory");
}
__device__ __forceinline__ void mbar_arrive(uint32_t a) {
    asm volatile("mbarrier.arrive.shared.b64 _, [%0];" :: "r"(a) : "memory");
}
__device__ __forceinline__ void mbar_wait(uint32_t a, uint32_t parity) {
    asm volatile(
        "{\n\t.reg .pred P;\n\t"
        "W_%=:\n\t"
        "mbarrier.try_wait.parity.shared.b64 P, [%0], %1;\n\t"
        "@P bra.uni D_%=;\n\t"
        "bra.uni W_%=;\n\t"
        "D_%=:\n\t}"
        :: "r"(a), "r"(parity) : "memory");
}
__device__ __forceinline__ void bulk_g2s(uint32_t dst, const void* src, uint32_t bytes,
                                         uint32_t mbar) {
    asm volatile(
        "cp.async.bulk.shared::cluster.global.mbarrier::complete_tx::bytes [%0], [%1], %2, [%3];"
        :: "r"(dst), "l"(src), "r"(bytes), "r"(mbar) : "memory");
}
__device__ __forceinline__ void ldsm_x4(uint32_t& r0, uint32_t& r1, uint32_t& r2, uint32_t& r3,
                                        uint32_t addr) {
    asm volatile("ldmatrix.sync.aligned.m8n8.x4.shared.b16 {%0,%1,%2,%3}, [%4];"
                 : "=r"(r0), "=r"(r1), "=r"(r2), "=r"(r3) : "r"(addr));
}
__device__ __forceinline__ void mma_acc(float* c,
                                        uint32_t a0, uint32_t a1, uint32_t a2, uint32_t a3,
                                        uint32_t b0, uint32_t b1) {
    asm volatile(
        "mma.sync.aligned.m16n8k16.row.col.f32.f16.f16.f32 "
        "{%0,%1,%2,%3}, {%4,%5,%6,%7}, {%8,%9}, {%0,%1,%2,%3};"
        : "+f"(c[0]), "+f"(c[1]), "+f"(c[2]), "+f"(c[3])
        : "r"(a0), "r"(a1), "r"(a2), "r"(a3), "r"(b0), "r"(b1));
}
__device__ __forceinline__ void mma_zc(float* d,
                                       uint32_t a0, uint32_t a1, uint32_t a2, uint32_t a3,
                                       uint32_t b0, uint32_t b1) {
    asm volatile(
        "mma.sync.aligned.m16n8k16.row.col.f32.f16.f16.f32 "
        "{%0,%1,%2,%3}, {%4,%5,%6,%7}, {%8,%9}, {%10,%11,%12,%13};"
        : "=f"(d[0]), "=f"(d[1]), "=f"(d[2]), "=f"(d[3])
        : "r"(a0), "r"(a1), "r"(a2), "r"(a3), "r"(b0), "r"(b1),
          "f"(0.f), "f"(0.f), "f"(0.f), "f"(0.f));
}

// ---------------------------------------------------------------------------
__global__ void __launch_bounds__(256) w2_prepass(const float* __restrict__ W2,
                                                  const float* __restrict__ b2) {
    const int h = blockIdx.x;
    const int tid = threadIdx.x;
    const float* src = (h < EH) ? (W2 + (size_t)h * (DD * DD)) : b2;
    unsigned char* dst = g_w2h + (size_t)h * STEP_BYTES;
    #pragma unroll
    for (int it = 0; it < 8; ++it) {
        int cid = tid + it * 256;
        int i = cid >> 4;
        int c = cid & 15;
        const float* s = src + (size_t)i * DD + c * 8;
        float4 a = *(const float4*)s;
        float4 b = *(const float4*)(s + 4);
        __half2 h0 = __floats2half2_rn(a.x, a.y);
        __half2 h1 = __floats2half2_rn(a.z, a.w);
        __half2 h2 = __floats2half2_rn(b.x, b.y);
        __half2 h3 = __floats2half2_rn(b.z, b.w);
        uint32_t off = (uint32_t)i * 256u + (swz_chunk((uint32_t)c, (uint32_t)(i & 7)) << 4);
        uint4 v;
        v.x = *(uint32_t*)&h0; v.y = *(uint32_t*)&h1;
        v.z = *(uint32_t*)&h2; v.w = *(uint32_t*)&h3;
        *(uint4*)(dst + off) = v;
    }
}

// ---------------------------------------------------------------------------
// Main: 128 edges/CTA, 256 threads, warps 4(M)x2(N) -> m32 x n64
// ---------------------------------------------------------------------------
__global__ void __launch_bounds__(256, 1)
edge_main(const float* __restrict__ hw, const float* __restrict__ ef,
          const float* __restrict__ W1, const float* __restrict__ b1,
          float* __restrict__ out, int n) {
    extern __shared__ __align__(1024) unsigned char smem[];
    const uint32_t smem_b = s2u(smem);
    const int tid = threadIdx.x;
    const int lane = tid & 31;
    const int wid = tid >> 5;
    const int warp_m = wid & 3;
    const int warp_n = wid >> 2;
    const int e0 = blockIdx.x * 128;

    if (tid == 0) {
        #pragma unroll
        for (int i = 0; i < SLOTS; ++i) {
            mbar_init(smem_b + MB_FULL(i), 1);
            mbar_init(smem_b + MB_EMPTY(i), 8);
        }
        asm volatile("fence.mbarrier_init.release.cluster;" ::: "memory");
    }
    __syncthreads();
    if (tid == 0) {
        #pragma unroll
        for (int i = 0; i < SLOTS; ++i) {
            mbar_expect_tx(smem_b + MB_FULL(i), STEP_BYTES);
            bulk_g2s(smem_b + W2_OFF + i * STEP_BYTES, g_w2h + (size_t)i * STEP_BYTES,
                     STEP_BYTES, smem_b + MB_FULL(i));
        }
    }

    // -------- stage ef / W1 / b1 --------
    {
        float* ef_s = (float*)(smem + SCR_EF);
        float* w1_s = (float*)(smem + SCR_W1);
        float* b1_s = (float*)(smem + SCR_B1);
        ((float4*)ef_s)[tid] = ((const float4*)(ef + (size_t)e0 * EDIM))[tid];
        ((float4*)ef_s)[tid + 256] = ((const float4*)(ef + (size_t)e0 * EDIM))[tid + 256];
        ((float4*)w1_s)[tid] = ((const float4*)W1)[tid];
        ((float4*)w1_s)[tid + 256] = ((const float4*)W1)[tid + 256];
        if (tid < EH) b1_s[tid] = b1[tid];
    }
    __syncthreads();

    // -------- MLP: Ht[h][e] fp32, step 128 = 1.0 --------
    {
        const float* ef_s = (const float*)(smem + SCR_EF);
        const float* w1_s = (const float*)(smem + SCR_W1);
        const float* b1_s = (const float*)(smem + SCR_B1);
        float* ht = (float*)(smem + HT_OFF);
        const int e = tid >> 1;
        const int part = tid & 1;
        float efr[EDIM];
        #pragma unroll
        for (int k = 0; k < EDIM; ++k) efr[k] = ef_s[e * EDIM + k];
        const int h0 = part * 64;
        #pragma unroll 4
        for (int hh = 0; hh < 64; hh += 4) {
            float4 acc4 = *(const float4*)(b1_s + h0 + hh);
            #pragma unroll
            for (int k = 0; k < EDIM; ++k) {
                float4 w = *(const float4*)(w1_s + k * EH + h0 + hh);
                acc4.x += efr[k] * w.x; acc4.y += efr[k] * w.y;
                acc4.z += efr[k] * w.z; acc4.w += efr[k] * w.w;
            }
            ht[(h0 + hh + 0) * 128 + e] = fmaxf(acc4.x, 0.f);
            ht[(h0 + hh + 1) * 128 + e] = fmaxf(acc4.y, 0.f);
            ht[(h0 + hh + 2) * 128 + e] = fmaxf(acc4.z, 0.f);
            ht[(h0 + hh + 3) * 128 + e] = fmaxf(acc4.w, 0.f);
        }
        if (part == 0) ht[128 * 128 + e] = 1.0f;
    }
    __syncthreads();

    // -------- hw fp16 image (overwrites scratch) --------
    {
        #pragma unroll
        for (int q = 0; q < 8; ++q) {
            int cid = tid + q * 256;
            int r = cid >> 4;
            int c = cid & 15;
            const float* s = hw + (size_t)(e0 + r) * DD + c * 8;
            float4 a = *(const float4*)s;
            float4 b = *(const float4*)(s + 4);
            __half2 h0 = __floats2half2_rn(a.x, a.y);
            __half2 h1 = __floats2half2_rn(a.z, a.w);
            __half2 h2 = __floats2half2_rn(b.x, b.y);
            __half2 h3 = __floats2half2_rn(b.z, b.w);
            uint32_t off = (uint32_t)r * 256u + (swz_chunk((uint32_t)c, (uint32_t)(r & 7)) << 4);
            uint4 v;
            v.x = *(uint32_t*)&h0; v.y = *(uint32_t*)&h1;
            v.z = *(uint32_t*)&h2; v.w = *(uint32_t*)&h3;
            *(uint4*)(smem + HW_HI + off) = v;
        }
    }
    __syncthreads();

    // -------- addressing --------
    const uint32_t rx = (uint32_t)(lane & 7);
    const uint32_t lhi = (uint32_t)(lane >> 4);
    const uint32_t aHi0 = smem_b + HW_HI + (uint32_t)(warp_m * 32 + (lane & 15)) * 256u;
    const uint32_t aHi1 = aHi0 + 16u * 256u;
    uint32_t bRow[4];
    #pragma unroll
    for (int g = 0; g < 4; ++g)
        bRow[g] = (uint32_t)(warp_n * 64 + g * 16 + (lane & 15)) * 256u;
    const float* ht = (const float*)(smem + HT_OFF);
    const int quad = lane >> 2;
    const int hrow = warp_m * 32 + quad;

    float acc[16][4];
    #pragma unroll
    for (int f = 0; f < 16; ++f)
        #pragma unroll
        for (int q = 0; q < 4; ++q) acc[f][q] = 0.f;

    // -------- main loop --------
    int slot = 0, use = 0;
    for (int s = 0; s < NSTEPS; ++s) {
        const uint32_t par = (uint32_t)use & 1u;
        mbar_wait(smem_b + MB_FULL(slot), par);

        const float hA0 = ht[s * 128 + hrow];
        const float hB0 = ht[s * 128 + hrow + 8];
        const float hA1 = ht[s * 128 + hrow + 16];
        const float hB1 = ht[s * 128 + hrow + 24];
        const uint32_t bSlot = smem_b + W2_OFF + slot * STEP_BYTES;

        float d[16][4];
        #pragma unroll
        for (int kt = 0; kt < 8; ++kt) {
            const uint32_t coff = swz_chunk((uint32_t)(kt * 2) + lhi, rx) << 4;
            uint32_t h00, h01, h02, h03, h10, h11, h12, h13;
            ldsm_x4(h00, h01, h02, h03, aHi0 + coff);
            ldsm_x4(h10, h11, h12, h13, aHi1 + coff);
            #pragma unroll
            for (int g = 0; g < 4; ++g) {
                uint32_t b0, b1r, b2, b3;
                ldsm_x4(b0, b1r, b2, b3, bSlot + bRow[g] + coff);
                float* d00 = d[g * 2 + 0];
                float* d01 = d[g * 2 + 1];
                float* d10 = d[8 + g * 2 + 0];
                float* d11 = d[8 + g * 2 + 1];
                if (kt == 0) {
                    mma_zc(d00, h00, h01, h02, h03, b0, b2);
                    mma_zc(d01, h00, h01, h02, h03, b1r, b3);
                    mma_zc(d10, h10, h11, h12, h13, b0, b2);
                    mma_zc(d11, h10, h11, h12, h13, b1r, b3);
                } else {
                    mma_acc(d00, h00, h01, h02, h03, b0, b2);
                    mma_acc(d01, h00, h01, h02, h03, b1r, b3);
                    mma_acc(d10, h10, h11, h12, h13, b0, b2);
                    mma_acc(d11, h10, h11, h12, h13, b1r, b3);
                }
            }
        }
        __syncwarp();
        if (lane == 0) mbar_arrive(smem_b + MB_EMPTY(slot));

        #pragma unroll
        for (int g2 = 0; g2 < 8; ++g2) {
            float* f0 = d[g2];
            float* f1 = d[8 + g2];
            acc[g2][0] += hA0 * f0[0];      acc[g2][1] += hA0 * f0[1];
            acc[g2][2] += hB0 * f0[2];      acc[g2][3] += hB0 * f0[3];
            acc[8 + g2][0] += hA1 * f1[0];  acc[8 + g2][1] += hA1 * f1[1];
            acc[8 + g2][2] += hB1 * f1[2];  acc[8 + g2][3] += hB1 * f1[3];
        }

        if (tid == 0 && s + SLOTS < NSTEPS) {
            mbar_wait(smem_b + MB_EMPTY(slot), par);
            mbar_expect_tx(smem_b + MB_FULL(slot), STEP_BYTES);
            bulk_g2s(smem_b + W2_OFF + slot * STEP_BYTES,
                     g_w2h + (size_t)(s + SLOTS) * STEP_BYTES, STEP_BYTES,
                     smem_b + MB_FULL(slot));
        }
        if (++slot == SLOTS) { slot = 0; ++use; }
    }

    // -------- epilogue --------
    #pragma unroll
    for (int mf = 0; mf < 2; ++mf) {
        const int er = e0 + warp_m * 32 + mf * 16 + quad;
        #pragma unroll
        for (int g = 0; g < 4; ++g)
            #pragma unroll
            for (int b = 0; b < 2; ++b) {
                const int f = mf * 8 + g * 2 + b;
                const int col = warp_n * 64 + g * 16 + b * 8 + (lane & 3) * 2;
                *(float2*)(out + (size_t)er * DD + col) = make_float2(acc[f][0], acc[f][1]);
                *(float2*)(out + (size_t)(er + 8) * DD + col) = make_float2(acc[f][2], acc[f][3]);
            }
    }
}

// ---------------------------------------------------------------------------
// Tail: 16 edges/CTA, 128 threads, 4 warps m16n32, full K
// ---------------------------------------------------------------------------
__global__ void __launch_bounds__(128, 1)
edge_tail(const float* __restrict__ hw, const float* __restrict__ ef,
          const float* __restrict__ W1, const float* __restrict__ b1,
          float* __restrict__ out, int n, int e_base) {
    extern __shared__ __align__(1024) unsigned char smem[];
    const uint32_t smem_b = s2u(smem);
    const int tid = threadIdx.x;
    const int lane = tid & 31;
    const int wid = tid >> 5;
    const int e0 = e_base + blockIdx.x * 16;

    if (tid == 0) {
        #pragma unroll
        for (int i = 0; i < SLOTS; ++i) {
            mbar_init(smem_b + MB_FULL(i), 1);
            mbar_init(smem_b + MB_EMPTY(i), 4);
        }
        asm volatile("fence.mbarrier_init.release.cluster;" ::: "memory");
    }
    __syncthreads();
    if (tid == 0) {
        #pragma unroll
        for (int i = 0; i < SLOTS; ++i) {
            mbar_expect_tx(smem_b + MB_FULL(i), STEP_BYTES);
            bulk_g2s(smem_b + T_W2 + i * STEP_BYTES, g_w2h + (size_t)i * STEP_BYTES,
                     STEP_BYTES, smem_b + MB_FULL(i));
        }
    }

    {
        float* ef_s = (float*)(smem + T_EF);
        float* w1_s = (float*)(smem + T_W1);
        float* b1_s = (float*)(smem + T_B1);
        if (tid < 64) {
            int e = tid >> 2;
            float4 v = make_float4(0.f, 0.f, 0.f, 0.f);
            if (e0 + e < n) v = *(const float4*)(ef + (size_t)(e0 + e) * EDIM + (tid & 3) * 4);
            ((float4*)ef_s)[tid] = v;
        }
        #pragma unroll
        for (int q = 0; q < 4; ++q)
            ((float4*)w1_s)[tid + q * 128] = ((const float4*)W1)[tid + q * 128];
        if (tid < EH) b1_s[tid] = b1[tid];
    }
    __syncthreads();

    {
        const float* ef_s = (const float*)(smem + T_EF);
        const float* w1_s = (const float*)(smem + T_W1);
        const float* b1_s = (const float*)(smem + T_B1);
        float* ht = (float*)(smem + T_HT);
        const int e = tid >> 3;
        const int part = tid & 7;
        float efr[EDIM];
        #pragma unroll
        for (int k = 0; k < EDIM; ++k) efr[k] = ef_s[e * EDIM + k];
        const int h0 = part * 16;
        #pragma unroll
        for (int hh = 0; hh < 16; hh += 4) {
            float4 acc4 = *(const float4*)(b1_s + h0 + hh);
            #pragma unroll
            for (int k = 0; k < EDIM; ++k) {
                float4 w = *(const float4*)(w1_s + k * EH + h0 + hh);
                acc4.x += efr[k] * w.x; acc4.y += efr[k] * w.y;
                acc4.z += efr[k] * w.z; acc4.w += efr[k] * w.w;
            }
            ht[(h0 + hh + 0) * 16 + e] = fmaxf(acc4.x, 0.f);
            ht[(h0 + hh + 1) * 16 + e] = fmaxf(acc4.y, 0.f);
            ht[(h0 + hh + 2) * 16 + e] = fmaxf(acc4.z, 0.f);
            ht[(h0 + hh + 3) * 16 + e] = fmaxf(acc4.w, 0.f);
        }
        if (part == 0) ht[128 * 16 + e] = 1.0f;
    }
    __syncthreads();

    {
        #pragma unroll
        for (int q = 0; q < 2; ++q) {
            int cid = tid + q * 128;
            int r = cid >> 4;
            int c = cid & 15;
            float4 a = make_float4(0.f, 0.f, 0.f, 0.f), b = a;
            if (e0 + r < n) {
                const float* s = hw + (size_t)(e0 + r) * DD + c * 8;
                a = *(const float4*)s;
                b = *(const float4*)(s + 4);
            }
            __half2 h0 = __floats2half2_rn(a.x, a.y);
            __half2 h1 = __floats2half2_rn(a.z, a.w);
            __half2 h2 = __floats2half2_rn(b.x, b.y);
            __half2 h3 = __floats2half2_rn(b.z, b.w);
            uint32_t off = (uint32_t)r * 256u + (swz_chunk((uint32_t)c, (uint32_t)(r & 7)) << 4);
            uint4 v;
            v.x = *(uint32_t*)&h0; v.y = *(uint32_t*)&h1;
            v.z = *(uint32_t*)&h2; v.w = *(uint32_t*)&h3;
            *(uint4*)(smem + T_HW_HI + off) = v;
        }
    }
    __syncthreads();

    const uint32_t rx = (uint32_t)(lane & 7);
    const uint32_t lhi = (uint32_t)(lane >> 4);
    const uint32_t aHi = smem_b + T_HW_HI + (uint32_t)(lane & 15) * 256u;
    uint32_t bRow[2];
    #pragma unroll
    for (int g = 0; g < 2; ++g)
        bRow[g] = (uint32_t)(wid * 32 + g * 16 + (lane & 15)) * 256u;
    const float* ht = (const float*)(smem + T_HT);
    const int quad = lane >> 2;

    float acc[4][4];
    #pragma unroll
    for (int f = 0; f < 4; ++f)
        #pragma unroll
        for (int q = 0; q < 4; ++q) acc[f][q] = 0.f;

    int slot = 0, use = 0;
    for (int s = 0; s < NSTEPS; ++s) {
        const uint32_t par = (uint32_t)use & 1u;
        mbar_wait(smem_b + MB_FULL(slot), par);

        const float hA = ht[s * 16 + quad];
        const float hB = ht[s * 16 + quad + 8];
        const uint32_t bSlot = smem_b + T_W2 + slot * STEP_BYTES;

        float d[4][4];
        #pragma unroll
        for (int kt = 0; kt < 8; ++kt) {
            const uint32_t coff = swz_chunk((uint32_t)(kt * 2) + lhi, rx) << 4;
            uint32_t h0r, h1r, h2r, h3r;
            ldsm_x4(h0r, h1r, h2r, h3r, aHi + coff);
            #pragma unroll
            for (int g = 0; g < 2; ++g) {
                uint32_t b0, b1r, b2, b3;
                ldsm_x4(b0, b1r, b2, b3, bSlot + bRow[g] + coff);
                float* d0 = d[g * 2 + 0];
                float* d1 = d[g * 2 + 1];
                if (kt == 0) {
                    mma_zc(d0, h0r, h1r, h2r, h3r, b0, b2);
                    mma_zc(d1, h0r, h1r, h2r, h3r, b1r, b3);
                } else {
                    mma_acc(d0, h0r, h1r, h2r, h3r, b0, b2);
                    mma_acc(d1, h0r, h1r, h2r, h3r, b1r, b3);
                }
            }
        }
        __syncwarp();
        if (lane == 0) mbar_arrive(smem_b + MB_EMPTY(slot));

        #pragma unroll
        for (int f = 0; f < 4; ++f) {
            acc[f][0] += hA * d[f][0];  acc[f][1] += hA * d[f][1];
            acc[f][2] += hB * d[f][2];  acc[f][3] += hB * d[f][3];
        }

        if (tid == 0 && s + SLOTS < NSTEPS) {
            mbar_wait(smem_b + MB_EMPTY(slot), par);
            mbar_expect_tx(smem_b + MB_FULL(slot), STEP_BYTES);
            bulk_g2s(smem_b + T_W2 + slot * STEP_BYTES,
                     g_w2h + (size_t)(s + SLOTS) * STEP_BYTES, STEP_BYTES,
                     smem_b + MB_FULL(slot));
        }
        if (++slot == SLOTS) { slot = 0; ++use; }
    }

    const int er = e0 + quad;
    #pragma unroll
    for (int g = 0; g < 2; ++g)
        #pragma unroll
        for (int b = 0; b < 2; ++b) {
            const int f = g * 2 + b;
            const int col = wid * 32 + g * 16 + b * 8 + (lane & 3) * 2;
            if (er < n)
                *(float2*)(out + (size_t)er * DD + col) = make_float2(acc[f][0], acc[f][1]);
            if (er + 8 < n)
                *(float2*)(out + (size_t)(er + 8) * DD + col) = make_float2(acc[f][2], acc[f][3]);
        }
}

// ---------------------------------------------------------------------------
extern "C" void kernel_launch(void* const* d_in, const int* in_sizes, int n_in,
                              void* d_out, int out_size) {
    const float* hw = (const float*)d_in[1];
    const float* ef = (const float*)d_in[2];
    const float* W1 = (const float*)d_in[3];
    const float* b1 = (const float*)d_in[4];
    const float* W2 = (const float*)d_in[5];
    const float* b2 = (const float*)d_in[6];
    const int n = in_sizes[1] / DD;

    w2_prepass<<<NSTEPS, 256>>>(W2, b2);

    int full = n / 128;
    if (full > 148) full = 148;
    if (full > 0) {
        cudaFuncSetAttribute(edge_main, cudaFuncAttributeMaxDynamicSharedMemorySize,
                             SMEM_TOTAL);
        edge_main<<<full, 256, SMEM_TOTAL>>>(hw, ef, W1, b1, (float*)d_out, n);
    }
    const int rem = n - full * 128;
    const int jobs = (rem + 15) / 16;
    if (jobs > 0) {
        cudaFuncSetAttribute(edge_tail, cudaFuncAttributeMaxDynamicSharedMemorySize,
                             TAIL_SMEM);
        edge_tail<<<jobs, 128, TAIL_SMEM>>>(hw, ef, W1, b1, (float*)d_out, n, full * 128);
    }
}

// round 5
// speedup vs baseline: 1.6588x; 1.4977x over previous
#include <cuda_runtime.h>
#include <cuda_fp16.h>
#include <stdint.h>

// ---------------------------------------------------------------------------
// EdgeNetwork: messages_e = sum_h H[e,h]*(hw_e @ W2[h]^T) + (hw_e @ b2-tile)
// H applied POST-MMA in fp32. Main: 148 CTAs x 128 edges, 512 threads,
// 16 warps m32n32 (4M x 4N) for 4 warps/SMSP latency hiding.
// Tail: 16-edge jobs, launched BEFORE main (independent edges) so ncu -s5
// captures edge_main. W2 fp16 image streamed via cp.async.bulk, 3 slots.
// ---------------------------------------------------------------------------

#define DD        128
#define EDIM      16
#define EH        128
#define NSTEPS    129
#define STEP_BYTES 32768
#define SLOTS     3

// ---- main smem layout ----
#define MB_FULL(i)  ((i)*8)
#define MB_EMPTY(i) (32 + (i)*8)
#define HW_HI       1024                 // 128 x 256B = 32768
#define HT_OFF      33792                // 129*128*4 = 66048 -> ends 99840
#define W2_OFF      100352               // 3 x 32768 -> ends 198656
#define SMEM_TOTAL  198656
// prologue scratch (inside HW_HI region, dead before hw image build)
#define SCR_EF      1024
#define SCR_W1      9216
#define SCR_B1      17408

// ---- tail smem layout ----
#define T_HW_HI     1024
#define T_HT        5120
#define T_W2        13824
#define T_EF        112128
#define T_W1        113152
#define T_B1        121344
#define TAIL_SMEM   121856

static __device__ __align__(128) unsigned char g_w2h[(size_t)NSTEPS * STEP_BYTES];

__device__ __forceinline__ uint32_t s2u(const void* p) {
    return (uint32_t)__cvta_generic_to_shared(p);
}
__device__ __forceinline__ uint32_t swz_chunk(uint32_t c, uint32_t r7) {
    return (c & 8u) | ((c & 7u) ^ r7);
}
__device__ __forceinline__ void mbar_init(uint32_t a, uint32_t cnt) {
    asm volatile("mbarrier.init.shared.b64 [%0], %1;" :: "r"(a), "r"(cnt) : "memory");
}
__device__ __forceinline__ void mbar_expect_tx(uint32_t a, uint32_t bytes) {
    asm volatile("mbarrier.arrive.expect_tx.shared.b64 _, [%0], %1;"
                 :: "r"(a), "r"(bytes) : "memory");
}
__device__ __forceinline__ void mbar_arrive(uint32_t a) {
    asm volatile("mbarrier.arrive.shared.b64 _, [%0];" :: "r"(a) : "memory");
}
__device__ __forceinline__ void mbar_wait(uint32_t a, uint32_t parity) {
    asm volatile(
        "{\n\t.reg .pred P;\n\t"
        "W_%=:\n\t"
        "mbarrier.try_wait.parity.shared.b64 P, [%0], %1;\n\t"
        "@P bra.uni D_%=;\n\t"
        "bra.uni W_%=;\n\t"
        "D_%=:\n\t}"
        :: "r"(a), "r"(parity) : "memory");
}
__device__ __forceinline__ void bulk_g2s(uint32_t dst, const void* src, uint32_t bytes,
                                         uint32_t mbar) {
    asm volatile(
        "cp.async.bulk.shared::cluster.global.mbarrier::complete_tx::bytes [%0], [%1], %2, [%3];"
        :: "r"(dst), "l"(src), "r"(bytes), "r"(mbar) : "memory");
}
__device__ __forceinline__ void ldsm_x4(uint32_t& r0, uint32_t& r1, uint32_t& r2, uint32_t& r3,
                                        uint32_t addr) {
    asm volatile("ldmatrix.sync.aligned.m8n8.x4.shared.b16 {%0,%1,%2,%3}, [%4];"
                 : "=r"(r0), "=r"(r1), "=r"(r2), "=r"(r3) : "r"(addr));
}
__device__ __forceinline__ void mma_acc(float* c,
                                        uint32_t a0, uint32_t a1, uint32_t a2, uint32_t a3,
                                        uint32_t b0, uint32_t b1) {
    asm volatile(
        "mma.sync.aligned.m16n8k16.row.col.f32.f16.f16.f32 "
        "{%0,%1,%2,%3}, {%4,%5,%6,%7}, {%8,%9}, {%0,%1,%2,%3};"
        : "+f"(c[0]), "+f"(c[1]), "+f"(c[2]), "+f"(c[3])
        : "r"(a0), "r"(a1), "r"(a2), "r"(a3), "r"(b0), "r"(b1));
}
__device__ __forceinline__ void mma_zc(float* d,
                                       uint32_t a0, uint32_t a1, uint32_t a2, uint32_t a3,
                                       uint32_t b0, uint32_t b1) {
    asm volatile(
        "mma.sync.aligned.m16n8k16.row.col.f32.f16.f16.f32 "
        "{%0,%1,%2,%3}, {%4,%5,%6,%7}, {%8,%9}, {%10,%11,%12,%13};"
        : "=f"(d[0]), "=f"(d[1]), "=f"(d[2]), "=f"(d[3])
        : "r"(a0), "r"(a1), "r"(a2), "r"(a3), "r"(b0), "r"(b1),
          "f"(0.f), "f"(0.f), "f"(0.f), "f"(0.f));
}

// ---------------------------------------------------------------------------
__global__ void __launch_bounds__(256) w2_prepass(const float* __restrict__ W2,
                                                  const float* __restrict__ b2) {
    const int h = blockIdx.x;
    const int tid = threadIdx.x;
    const float* src = (h < EH) ? (W2 + (size_t)h * (DD * DD)) : b2;
    unsigned char* dst = g_w2h + (size_t)h * STEP_BYTES;
    #pragma unroll
    for (int it = 0; it < 8; ++it) {
        int cid = tid + it * 256;
        int i = cid >> 4;
        int c = cid & 15;
        const float* s = src + (size_t)i * DD + c * 8;
        float4 a = *(const float4*)s;
        float4 b = *(const float4*)(s + 4);
        __half2 h0 = __floats2half2_rn(a.x, a.y);
        __half2 h1 = __floats2half2_rn(a.z, a.w);
        __half2 h2 = __floats2half2_rn(b.x, b.y);
        __half2 h3 = __floats2half2_rn(b.z, b.w);
        uint32_t off = (uint32_t)i * 256u + (swz_chunk((uint32_t)c, (uint32_t)(i & 7)) << 4);
        uint4 v;
        v.x = *(uint32_t*)&h0; v.y = *(uint32_t*)&h1;
        v.z = *(uint32_t*)&h2; v.w = *(uint32_t*)&h3;
        *(uint4*)(dst + off) = v;
    }
}

// ---------------------------------------------------------------------------
// Main: 128 edges/CTA, 512 threads, 16 warps 4(M)x4(N) -> m32 x n32
// ---------------------------------------------------------------------------
__global__ void __launch_bounds__(512, 1)
edge_main(const float* __restrict__ hw, const float* __restrict__ ef,
          const float* __restrict__ W1, const float* __restrict__ b1,
          float* __restrict__ out, int n) {
    extern __shared__ __align__(1024) unsigned char smem[];
    const uint32_t smem_b = s2u(smem);
    const int tid = threadIdx.x;
    const int lane = tid & 31;
    const int wid = tid >> 5;
    const int warp_m = wid & 3;
    const int warp_n = wid >> 2;       // 0..3
    const int e0 = blockIdx.x * 128;

    if (tid == 0) {
        #pragma unroll
        for (int i = 0; i < SLOTS; ++i) {
            mbar_init(smem_b + MB_FULL(i), 1);
            mbar_init(smem_b + MB_EMPTY(i), 16);
        }
        asm volatile("fence.mbarrier_init.release.cluster;" ::: "memory");
    }
    __syncthreads();
    if (tid == 0) {
        #pragma unroll
        for (int i = 0; i < SLOTS; ++i) {
            mbar_expect_tx(smem_b + MB_FULL(i), STEP_BYTES);
            bulk_g2s(smem_b + W2_OFF + i * STEP_BYTES, g_w2h + (size_t)i * STEP_BYTES,
                     STEP_BYTES, smem_b + MB_FULL(i));
        }
    }

    // -------- stage ef / W1 / b1 --------
    {
        float* ef_s = (float*)(smem + SCR_EF);
        float* w1_s = (float*)(smem + SCR_W1);
        float* b1_s = (float*)(smem + SCR_B1);
        ((float4*)ef_s)[tid] = ((const float4*)(ef + (size_t)e0 * EDIM))[tid];
        ((float4*)w1_s)[tid] = ((const float4*)W1)[tid];
        if (tid < EH) b1_s[tid] = b1[tid];
    }
    __syncthreads();

    // -------- MLP: Ht[h][e] fp32, step 128 = 1.0 --------
    {
        const float* ef_s = (const float*)(smem + SCR_EF);
        const float* w1_s = (const float*)(smem + SCR_W1);
        const float* b1_s = (const float*)(smem + SCR_B1);
        float* ht = (float*)(smem + HT_OFF);
        const int e = tid >> 2;          // 0..127
        const int part = tid & 3;        // 32 h each
        float efr[EDIM];
        #pragma unroll
        for (int k = 0; k < EDIM; ++k) efr[k] = ef_s[e * EDIM + k];
        const int h0 = part * 32;
        #pragma unroll 8
        for (int hh = 0; hh < 32; hh += 4) {
            float4 acc4 = *(const float4*)(b1_s + h0 + hh);
            #pragma unroll
            for (int k = 0; k < EDIM; ++k) {
                float4 w = *(const float4*)(w1_s + k * EH + h0 + hh);
                acc4.x += efr[k] * w.x; acc4.y += efr[k] * w.y;
                acc4.z += efr[k] * w.z; acc4.w += efr[k] * w.w;
            }
            ht[(h0 + hh + 0) * 128 + e] = fmaxf(acc4.x, 0.f);
            ht[(h0 + hh + 1) * 128 + e] = fmaxf(acc4.y, 0.f);
            ht[(h0 + hh + 2) * 128 + e] = fmaxf(acc4.z, 0.f);
            ht[(h0 + hh + 3) * 128 + e] = fmaxf(acc4.w, 0.f);
        }
        if (part == 0) ht[128 * 128 + e] = 1.0f;
    }
    __syncthreads();

    // -------- hw fp16 image (overwrites scratch) --------
    {
        #pragma unroll
        for (int q = 0; q < 4; ++q) {
            int cid = tid + q * 512;
            int r = cid >> 4;
            int c = cid & 15;
            const float* s = hw + (size_t)(e0 + r) * DD + c * 8;
            float4 a = *(const float4*)s;
            float4 b = *(const float4*)(s + 4);
            __half2 h0 = __floats2half2_rn(a.x, a.y);
            __half2 h1 = __floats2half2_rn(a.z, a.w);
            __half2 h2 = __floats2half2_rn(b.x, b.y);
            __half2 h3 = __floats2half2_rn(b.z, b.w);
            uint32_t off = (uint32_t)r * 256u + (swz_chunk((uint32_t)c, (uint32_t)(r & 7)) << 4);
            uint4 v;
            v.x = *(uint32_t*)&h0; v.y = *(uint32_t*)&h1;
            v.z = *(uint32_t*)&h2; v.w = *(uint32_t*)&h3;
            *(uint4*)(smem + HW_HI + off) = v;
        }
    }
    __syncthreads();

    // -------- addressing --------
    const uint32_t rx = (uint32_t)(lane & 7);
    const uint32_t lhi = (uint32_t)(lane >> 4);
    const uint32_t aBase0 = smem_b + HW_HI + (uint32_t)(warp_m * 32 + (lane & 15)) * 256u;
    const uint32_t aBase1 = aBase0 + 16u * 256u;
    uint32_t bRow[2];
    #pragma unroll
    for (int g = 0; g < 2; ++g)
        bRow[g] = (uint32_t)(warp_n * 32 + g * 16 + (lane & 15)) * 256u;
    const float* ht = (const float*)(smem + HT_OFF);
    const int quad = lane >> 2;
    const int hrow = warp_m * 32 + quad;

    float acc[2][4][4];
    #pragma unroll
    for (int mf = 0; mf < 2; ++mf)
        #pragma unroll
        for (int f = 0; f < 4; ++f)
            #pragma unroll
            for (int q = 0; q < 4; ++q) acc[mf][f][q] = 0.f;

    // -------- main loop --------
    int slot = 0, use = 0;
    for (int s = 0; s < NSTEPS; ++s) {
        const uint32_t par = (uint32_t)use & 1u;
        mbar_wait(smem_b + MB_FULL(slot), par);

        const float hA0 = ht[s * 128 + hrow];
        const float hB0 = ht[s * 128 + hrow + 8];
        const float hA1 = ht[s * 128 + hrow + 16];
        const float hB1 = ht[s * 128 + hrow + 24];
        const uint32_t bSlot = smem_b + W2_OFF + slot * STEP_BYTES;

        float d[2][4][4];
        #pragma unroll
        for (int kt = 0; kt < 8; ++kt) {
            const uint32_t coff = swz_chunk((uint32_t)(kt * 2) + lhi, rx) << 4;
            uint32_t a00, a01, a02, a03, a10, a11, a12, a13;
            ldsm_x4(a00, a01, a02, a03, aBase0 + coff);
            ldsm_x4(a10, a11, a12, a13, aBase1 + coff);
            #pragma unroll
            for (int g = 0; g < 2; ++g) {
                uint32_t b0, b1r, b2, b3;
                ldsm_x4(b0, b1r, b2, b3, bSlot + bRow[g] + coff);
                if (kt == 0) {
                    mma_zc(d[0][g * 2 + 0], a00, a01, a02, a03, b0, b2);
                    mma_zc(d[0][g * 2 + 1], a00, a01, a02, a03, b1r, b3);
                    mma_zc(d[1][g * 2 + 0], a10, a11, a12, a13, b0, b2);
                    mma_zc(d[1][g * 2 + 1], a10, a11, a12, a13, b1r, b3);
                } else {
                    mma_acc(d[0][g * 2 + 0], a00, a01, a02, a03, b0, b2);
                    mma_acc(d[0][g * 2 + 1], a00, a01, a02, a03, b1r, b3);
                    mma_acc(d[1][g * 2 + 0], a10, a11, a12, a13, b0, b2);
                    mma_acc(d[1][g * 2 + 1], a10, a11, a12, a13, b1r, b3);
                }
            }
        }
        __syncwarp();
        if (lane == 0) mbar_arrive(smem_b + MB_EMPTY(slot));

        #pragma unroll
        for (int f = 0; f < 4; ++f) {
            acc[0][f][0] += hA0 * d[0][f][0];  acc[0][f][1] += hA0 * d[0][f][1];
            acc[0][f][2] += hB0 * d[0][f][2];  acc[0][f][3] += hB0 * d[0][f][3];
            acc[1][f][0] += hA1 * d[1][f][0];  acc[1][f][1] += hA1 * d[1][f][1];
            acc[1][f][2] += hB1 * d[1][f][2];  acc[1][f][3] += hB1 * d[1][f][3];
        }

        if (tid == 0 && s + SLOTS < NSTEPS) {
            mbar_wait(smem_b + MB_EMPTY(slot), par);
            mbar_expect_tx(smem_b + MB_FULL(slot), STEP_BYTES);
            bulk_g2s(smem_b + W2_OFF + slot * STEP_BYTES,
                     g_w2h + (size_t)(s + SLOTS) * STEP_BYTES, STEP_BYTES,
                     smem_b + MB_FULL(slot));
        }
        if (++slot == SLOTS) { slot = 0; ++use; }
    }

    // -------- epilogue --------
    #pragma unroll
    for (int mf = 0; mf < 2; ++mf) {
        const int er = e0 + warp_m * 32 + mf * 16 + quad;
        #pragma unroll
        for (int g = 0; g < 2; ++g)
            #pragma unroll
            for (int b = 0; b < 2; ++b) {
                const int f = g * 2 + b;
                const int col = warp_n * 32 + g * 16 + b * 8 + (lane & 3) * 2;
                *(float2*)(out + (size_t)er * DD + col) =
                    make_float2(acc[mf][f][0], acc[mf][f][1]);
                *(float2*)(out + (size_t)(er + 8) * DD + col) =
                    make_float2(acc[mf][f][2], acc[mf][f][3]);
            }
    }
}

// ---------------------------------------------------------------------------
// Tail: 16 edges/CTA, 128 threads, 4 warps m16n32, full K
// ---------------------------------------------------------------------------
__global__ void __launch_bounds__(128, 1)
edge_tail(const float* __restrict__ hw, const float* __restrict__ ef,
          const float* __restrict__ W1, const float* __restrict__ b1,
          float* __restrict__ out, int n, int e_base) {
    extern __shared__ __align__(1024) unsigned char smem[];
    const uint32_t smem_b = s2u(smem);
    const int tid = threadIdx.x;
    const int lane = tid & 31;
    const int wid = tid >> 5;
    const int e0 = e_base + blockIdx.x * 16;

    if (tid == 0) {
        #pragma unroll
        for (int i = 0; i < SLOTS; ++i) {
            mbar_init(smem_b + MB_FULL(i), 1);
            mbar_init(smem_b + MB_EMPTY(i), 4);
        }
        asm volatile("fence.mbarrier_init.release.cluster;" ::: "memory");
    }
    __syncthreads();
    if (tid == 0) {
        #pragma unroll
        for (int i = 0; i < SLOTS; ++i) {
            mbar_expect_tx(smem_b + MB_FULL(i), STEP_BYTES);
            bulk_g2s(smem_b + T_W2 + i * STEP_BYTES, g_w2h + (size_t)i * STEP_BYTES,
                     STEP_BYTES, smem_b + MB_FULL(i));
        }
    }

    {
        float* ef_s = (float*)(smem + T_EF);
        float* w1_s = (float*)(smem + T_W1);
        float* b1_s = (float*)(smem + T_B1);
        if (tid < 64) {
            int e = tid >> 2;
            float4 v = make_float4(0.f, 0.f, 0.f, 0.f);
            if (e0 + e < n) v = *(const float4*)(ef + (size_t)(e0 + e) * EDIM + (tid & 3) * 4);
            ((float4*)ef_s)[tid] = v;
        }
        #pragma unroll
        for (int q = 0; q < 4; ++q)
            ((float4*)w1_s)[tid + q * 128] = ((const float4*)W1)[tid + q * 128];
        if (tid < EH) b1_s[tid] = b1[tid];
    }
    __syncthreads();

    {
        const float* ef_s = (const float*)(smem + T_EF);
        const float* w1_s = (const float*)(smem + T_W1);
        const float* b1_s = (const float*)(smem + T_B1);
        float* ht = (float*)(smem + T_HT);
        const int e = tid >> 3;
        const int part = tid & 7;
        float efr[EDIM];
        #pragma unroll
        for (int k = 0; k < EDIM; ++k) efr[k] = ef_s[e * EDIM + k];
        const int h0 = part * 16;
        #pragma unroll
        for (int hh = 0; hh < 16; hh += 4) {
            float4 acc4 = *(const float4*)(b1_s + h0 + hh);
            #pragma unroll
            for (int k = 0; k < EDIM; ++k) {
                float4 w = *(const float4*)(w1_s + k * EH + h0 + hh);
                acc4.x += efr[k] * w.x; acc4.y += efr[k] * w.y;
                acc4.z += efr[k] * w.z; acc4.w += efr[k] * w.w;
            }
            ht[(h0 + hh + 0) * 16 + e] = fmaxf(acc4.x, 0.f);
            ht[(h0 + hh + 1) * 16 + e] = fmaxf(acc4.y, 0.f);
            ht[(h0 + hh + 2) * 16 + e] = fmaxf(acc4.z, 0.f);
            ht[(h0 + hh + 3) * 16 + e] = fmaxf(acc4.w, 0.f);
        }
        if (part == 0) ht[128 * 16 + e] = 1.0f;
    }
    __syncthreads();

    {
        #pragma unroll
        for (int q = 0; q < 2; ++q) {
            int cid = tid + q * 128;
            int r = cid >> 4;
            int c = cid & 15;
            float4 a = make_float4(0.f, 0.f, 0.f, 0.f), b = a;
            if (e0 + r < n) {
                const float* s = hw + (size_t)(e0 + r) * DD + c * 8;
                a = *(const float4*)s;
                b = *(const float4*)(s + 4);
            }
            __half2 h0 = __floats2half2_rn(a.x, a.y);
            __half2 h1 = __floats2half2_rn(a.z, a.w);
            __half2 h2 = __floats2half2_rn(b.x, b.y);
            __half2 h3 = __floats2half2_rn(b.z, b.w);
            uint32_t off = (uint32_t)r * 256u + (swz_chunk((uint32_t)c, (uint32_t)(r & 7)) << 4);
            uint4 v;
            v.x = *(uint32_t*)&h0; v.y = *(uint32_t*)&h1;
            v.z = *(uint32_t*)&h2; v.w = *(uint32_t*)&h3;
            *(uint4*)(smem + T_HW_HI + off) = v;
        }
    }
    __syncthreads();

    const uint32_t rx = (uint32_t)(lane & 7);
    const uint32_t lhi = (uint32_t)(lane >> 4);
    const uint32_t aHi = smem_b + T_HW_HI + (uint32_t)(lane & 15) * 256u;
    uint32_t bRow[2];
    #pragma unroll
    for (int g = 0; g < 2; ++g)
        bRow[g] = (uint32_t)(wid * 32 + g * 16 + (lane & 15)) * 256u;
    const float* ht = (const float*)(smem + T_HT);
    const int quad = lane >> 2;

    float acc[4][4];
    #pragma unroll
    for (int f = 0; f < 4; ++f)
        #pragma unroll
        for (int q = 0; q < 4; ++q) acc[f][q] = 0.f;

    int slot = 0, use = 0;
    for (int s = 0; s < NSTEPS; ++s) {
        const uint32_t par = (uint32_t)use & 1u;
        mbar_wait(smem_b + MB_FULL(slot), par);

        const float hA = ht[s * 16 + quad];
        const float hB = ht[s * 16 + quad + 8];
        const uint32_t bSlot = smem_b + T_W2 + slot * STEP_BYTES;

        float d[4][4];
        #pragma unroll
        for (int kt = 0; kt < 8; ++kt) {
            const uint32_t coff = swz_chunk((uint32_t)(kt * 2) + lhi, rx) << 4;
            uint32_t h0r, h1r, h2r, h3r;
            ldsm_x4(h0r, h1r, h2r, h3r, aHi + coff);
            #pragma unroll
            for (int g = 0; g < 2; ++g) {
                uint32_t b0, b1r, b2, b3;
                ldsm_x4(b0, b1r, b2, b3, bSlot + bRow[g] + coff);
                float* d0 = d[g * 2 + 0];
                float* d1 = d[g * 2 + 1];
                if (kt == 0) {
                    mma_zc(d0, h0r, h1r, h2r, h3r, b0, b2);
                    mma_zc(d1, h0r, h1r, h2r, h3r, b1r, b3);
                } else {
                    mma_acc(d0, h0r, h1r, h2r, h3r, b0, b2);
                    mma_acc(d1, h0r, h1r, h2r, h3r, b1r, b3);
                }
            }
        }
        __syncwarp();
        if (lane == 0) mbar_arrive(smem_b + MB_EMPTY(slot));

        #pragma unroll
        for (int f = 0; f < 4; ++f) {
            acc[f][0] += hA * d[f][0];  acc[f][1] += hA * d[f][1];
            acc[f][2] += hB * d[f][2];  acc[f][3] += hB * d[f][3];
        }

        if (tid == 0 && s + SLOTS < NSTEPS) {
            mbar_wait(smem_b + MB_EMPTY(slot), par);
            mbar_expect_tx(smem_b + MB_FULL(slot), STEP_BYTES);
            bulk_g2s(smem_b + T_W2 + slot * STEP_BYTES,
                     g_w2h + (size_t)(s + SLOTS) * STEP_BYTES, STEP_BYTES,
                     smem_b + MB_FULL(slot));
        }
        if (++slot == SLOTS) { slot = 0; ++use; }
    }

    const int er = e0 + quad;
    #pragma unroll
    for (int g = 0; g < 2; ++g)
        #pragma unroll
        for (int b = 0; b < 2; ++b) {
            const int f = g * 2 + b;
            const int col = wid * 32 + g * 16 + b * 8 + (lane & 3) * 2;
            if (er < n)
                *(float2*)(out + (size_t)er * DD + col) = make_float2(acc[f][0], acc[f][1]);
            if (er + 8 < n)
                *(float2*)(out + (size_t)(er + 8) * DD + col) = make_float2(acc[f][2], acc[f][3]);
        }
}

// ---------------------------------------------------------------------------
extern "C" void kernel_launch(void* const* d_in, const int* in_sizes, int n_in,
                              void* d_out, int out_size) {
    const float* hw = (const float*)d_in[1];
    const float* ef = (const float*)d_in[2];
    const float* W1 = (const float*)d_in[3];
    const float* b1 = (const float*)d_in[4];
    const float* W2 = (const float*)d_in[5];
    const float* b2 = (const float*)d_in[6];
    const int n = in_sizes[1] / DD;

    w2_prepass<<<NSTEPS, 256>>>(W2, b2);

    int full = n / 128;
    if (full > 148) full = 148;
    const int rem = n - full * 128;
    const int jobs = (rem + 15) / 16;
    // tail BEFORE main: independent edge ranges; puts edge_main at launch #6
    // within two replays so ncu -s 5 -c 1 profiles it.
    if (jobs > 0) {
        cudaFuncSetAttribute(edge_tail, cudaFuncAttributeMaxDynamicSharedMemorySize,
                             TAIL_SMEM);
        edge_tail<<<jobs, 128, TAIL_SMEM>>>(hw, ef, W1, b1, (float*)d_out, n, full * 128);
    }
    if (full > 0) {
        cudaFuncSetAttribute(edge_main, cudaFuncAttributeMaxDynamicSharedMemorySize,
                             SMEM_TOTAL);
        edge_main<<<full, 512, SMEM_TOTAL>>>(hw, ef, W1, b1, (float*)d_out, n);
    }
}

// round 7
// speedup vs baseline: 1.8616x; 1.1223x over previous
#include <cuda_runtime.h>
#include <cuda_fp16.h>
#include <stdint.h>

// ---------------------------------------------------------------------------
// EdgeNetwork: messages_e = sum_h H[e,h]*(hw_e @ W2[h]^T) + (hw_e @ b2-tile)
// H applied POST-MMA in fp32. A (= hw) fragments are step-invariant ->
// register-resident (loaded once via ldmatrix), eliminating A smem traffic.
// Main: 148 CTAs x 128 edges, 256 threads, 8 warps m32n64, two n32 passes.
// Tail: 66 jobs x 16 edges, 256 threads, 8 warps m16n16 each.
// W2 fp16 image (prepass) streamed via cp.async.bulk, 3 slots.
// ---------------------------------------------------------------------------

#define DD        128
#define EDIM      16
#define EH        128
#define NSTEPS    129
#define STEP_BYTES 32768
#define SLOTS     3

// ---- main smem layout ----
#define MB_FULL(i)  ((i)*8)
#define MB_EMPTY(i) (32 + (i)*8)
#define HW_HI       1024                 // 128 x 256B = 32768
#define HT_OFF      33792                // 129*128*4 = 66048 -> ends 99840
#define W2_OFF      100352               // 3 x 32768 -> ends 198656
#define SMEM_TOTAL  198656
#define SCR_EF      1024
#define SCR_W1      9216
#define SCR_B1      17408

// ---- tail smem layout ----
#define T_HW       1024                  // 16 x 256B = 4096
#define T_HT       5120                  // 129*16*4 = 8256 -> 13376
#define T_W2       13824                 // 3 x 32768 -> 112128
#define T_EF       112128
#define T_W1       113152
#define T_B1       121344
#define TAIL_SMEM  121856

static __device__ __align__(128) unsigned char g_w2h[(size_t)NSTEPS * STEP_BYTES];

__device__ __forceinline__ uint32_t s2u(const void* p) {
    return (uint32_t)__cvta_generic_to_shared(p);
}
__device__ __forceinline__ uint32_t swz_chunk(uint32_t c, uint32_t r7) {
    return (c & 8u) | ((c & 7u) ^ r7);
}
__device__ __forceinline__ void mbar_init(uint32_t a, uint32_t cnt) {
    asm volatile("mbarrier.init.shared.b64 [%0], %1;" :: "r"(a), "r"(cnt) : "memory");
}
__device__ __forceinline__ void mbar_expect_tx(uint32_t a, uint32_t bytes) {
    asm volatile("mbarrier.arrive.expect_tx.shared.b64 _, [%0], %1;"
                 :: "r"(a), "r"(bytes) : "memory");
}
__device__ __forceinline__ void mbar_arrive(uint32_t a) {
    asm volatile("mbarrier.arrive.shared.b64 _, [%0];" :: "r"(a) : "memory");
}
__device__ __forceinline__ void mbar_wait(uint32_t a, uint32_t parity) {
    asm volatile(
        "{\n\t.reg .pred P;\n\t"
        "W_%=:\n\t"
        "mbarrier.try_wait.parity.shared.b64 P, [%0], %1;\n\t"
        "@P bra.uni D_%=;\n\t"
        "bra.uni W_%=;\n\t"
        "D_%=:\n\t}"
        :: "r"(a), "r"(parity) : "memory");
}
__device__ __forceinline__ void bulk_g2s(uint32_t dst, const void* src, uint32_t bytes,
                                         uint32_t mbar) {
    asm volatile(
        "cp.async.bulk.shared::cluster.global.mbarrier::complete_tx::bytes [%0], [%1], %2, [%3];"
        :: "r"(dst), "l"(src), "r"(bytes), "r"(mbar) : "memory");
}
__device__ __forceinline__ void ldsm_x4(uint32_t& r0, uint32_t& r1, uint32_t& r2, uint32_t& r3,
                                        uint32_t addr) {
    asm volatile("ldmatrix.sync.aligned.m8n8.x4.shared.b16 {%0,%1,%2,%3}, [%4];"
                 : "=r"(r0), "=r"(r1), "=r"(r2), "=r"(r3) : "r"(addr));
}
__device__ __forceinline__ void mma_acc(float* c, const uint32_t* a,
                                        uint32_t b0, uint32_t b1) {
    asm volatile(
        "mma.sync.aligned.m16n8k16.row.col.f32.f16.f16.f32 "
        "{%0,%1,%2,%3}, {%4,%5,%6,%7}, {%8,%9}, {%0,%1,%2,%3};"
        : "+f"(c[0]), "+f"(c[1]), "+f"(c[2]), "+f"(c[3])
        : "r"(a[0]), "r"(a[1]), "r"(a[2]), "r"(a[3]), "r"(b0), "r"(b1));
}
__device__ __forceinline__ void mma_zc(float* d, const uint32_t* a,
                                       uint32_t b0, uint32_t b1) {
    asm volatile(
        "mma.sync.aligned.m16n8k16.row.col.f32.f16.f16.f32 "
        "{%0,%1,%2,%3}, {%4,%5,%6,%7}, {%8,%9}, {%10,%11,%12,%13};"
        : "=f"(d[0]), "=f"(d[1]), "=f"(d[2]), "=f"(d[3])
        : "r"(a[0]), "r"(a[1]), "r"(a[2]), "r"(a[3]), "r"(b0), "r"(b1),
          "f"(0.f), "f"(0.f), "f"(0.f), "f"(0.f));
}

// ---------------------------------------------------------------------------
__global__ void __launch_bounds__(256) w2_prepass(const float* __restrict__ W2,
                                                  const float* __restrict__ b2) {
    const int h = blockIdx.x;
    const int tid = threadIdx.x;
    const float* src = (h < EH) ? (W2 + (size_t)h * (DD * DD)) : b2;
    unsigned char* dst = g_w2h + (size_t)h * STEP_BYTES;
    #pragma unroll
    for (int it = 0; it < 8; ++it) {
        int cid = tid + it * 256;
        int i = cid >> 4;
        int c = cid & 15;
        const float* s = src + (size_t)i * DD + c * 8;
        float4 a = *(const float4*)s;
        float4 b = *(const float4*)(s + 4);
        __half2 h0 = __floats2half2_rn(a.x, a.y);
        __half2 h1 = __floats2half2_rn(a.z, a.w);
        __half2 h2 = __floats2half2_rn(b.x, b.y);
        __half2 h3 = __floats2half2_rn(b.z, b.w);
        uint32_t off = (uint32_t)i * 256u + (swz_chunk((uint32_t)c, (uint32_t)(i & 7)) << 4);
        uint4 v;
        v.x = *(uint32_t*)&h0; v.y = *(uint32_t*)&h1;
        v.z = *(uint32_t*)&h2; v.w = *(uint32_t*)&h3;
        *(uint4*)(dst + off) = v;
    }
}

// ---------------------------------------------------------------------------
// Main: 128 edges/CTA, 256 threads, 8 warps 4(M)x2(N) -> m32 x n64,
// A register-resident, each step = two n32 passes.
// ---------------------------------------------------------------------------
__global__ void __launch_bounds__(256, 1)
edge_main(const float* __restrict__ hw, const float* __restrict__ ef,
          const float* __restrict__ W1, const float* __restrict__ b1,
          float* __restrict__ out, int n) {
    extern __shared__ __align__(1024) unsigned char smem[];
    const uint32_t smem_b = s2u(smem);
    const int tid = threadIdx.x;
    const int lane = tid & 31;
    const int wid = tid >> 5;
    const int warp_m = wid & 3;
    const int warp_n = wid >> 2;       // 0..1
    const int e0 = blockIdx.x * 128;

    if (tid == 0) {
        #pragma unroll
        for (int i = 0; i < SLOTS; ++i) {
            mbar_init(smem_b + MB_FULL(i), 1);
            mbar_init(smem_b + MB_EMPTY(i), 8);
        }
        asm volatile("fence.mbarrier_init.release.cluster;" ::: "memory");
    }
    __syncthreads();
    if (tid == 0) {
        #pragma unroll
        for (int i = 0; i < SLOTS; ++i) {
            mbar_expect_tx(smem_b + MB_FULL(i), STEP_BYTES);
            bulk_g2s(smem_b + W2_OFF + i * STEP_BYTES, g_w2h + (size_t)i * STEP_BYTES,
                     STEP_BYTES, smem_b + MB_FULL(i));
        }
    }

    // -------- stage ef / W1 / b1 --------
    {
        float* ef_s = (float*)(smem + SCR_EF);
        float* w1_s = (float*)(smem + SCR_W1);
        float* b1_s = (float*)(smem + SCR_B1);
        ((float4*)ef_s)[tid] = ((const float4*)(ef + (size_t)e0 * EDIM))[tid];
        ((float4*)ef_s)[tid + 256] = ((const float4*)(ef + (size_t)e0 * EDIM))[tid + 256];
        ((float4*)w1_s)[tid] = ((const float4*)W1)[tid];
        ((float4*)w1_s)[tid + 256] = ((const float4*)W1)[tid + 256];
        if (tid < EH) b1_s[tid] = b1[tid];
    }
    __syncthreads();

    // -------- MLP: Ht[h][e] fp32, step 128 = 1.0 --------
    {
        const float* ef_s = (const float*)(smem + SCR_EF);
        const float* w1_s = (const float*)(smem + SCR_W1);
        const float* b1_s = (const float*)(smem + SCR_B1);
        float* ht = (float*)(smem + HT_OFF);
        const int e = tid >> 1;
        const int part = tid & 1;
        float efr[EDIM];
        #pragma unroll
        for (int k = 0; k < EDIM; ++k) efr[k] = ef_s[e * EDIM + k];
        const int h0 = part * 64;
        #pragma unroll 4
        for (int hh = 0; hh < 64; hh += 4) {
            float4 acc4 = *(const float4*)(b1_s + h0 + hh);
            #pragma unroll
            for (int k = 0; k < EDIM; ++k) {
                float4 w = *(const float4*)(w1_s + k * EH + h0 + hh);
                acc4.x += efr[k] * w.x; acc4.y += efr[k] * w.y;
                acc4.z += efr[k] * w.z; acc4.w += efr[k] * w.w;
            }
            ht[(h0 + hh + 0) * 128 + e] = fmaxf(acc4.x, 0.f);
            ht[(h0 + hh + 1) * 128 + e] = fmaxf(acc4.y, 0.f);
            ht[(h0 + hh + 2) * 128 + e] = fmaxf(acc4.z, 0.f);
            ht[(h0 + hh + 3) * 128 + e] = fmaxf(acc4.w, 0.f);
        }
        if (part == 0) ht[128 * 128 + e] = 1.0f;
    }
    __syncthreads();

    // -------- hw fp16 image --------
    {
        #pragma unroll
        for (int q = 0; q < 8; ++q) {
            int cid = tid + q * 256;
            int r = cid >> 4;
            int c = cid & 15;
            const float* s = hw + (size_t)(e0 + r) * DD + c * 8;
            float4 a = *(const float4*)s;
            float4 b = *(const float4*)(s + 4);
            __half2 h0 = __floats2half2_rn(a.x, a.y);
            __half2 h1 = __floats2half2_rn(a.z, a.w);
            __half2 h2 = __floats2half2_rn(b.x, b.y);
            __half2 h3 = __floats2half2_rn(b.z, b.w);
            uint32_t off = (uint32_t)r * 256u + (swz_chunk((uint32_t)c, (uint32_t)(r & 7)) << 4);
            uint4 v;
            v.x = *(uint32_t*)&h0; v.y = *(uint32_t*)&h1;
            v.z = *(uint32_t*)&h2; v.w = *(uint32_t*)&h3;
            *(uint4*)(smem + HW_HI + off) = v;
        }
    }
    __syncthreads();

    // -------- load A fragments into registers (step-invariant) --------
    const uint32_t rx = (uint32_t)(lane & 7);
    const uint32_t lhi = (uint32_t)(lane >> 4);
    uint32_t coffv[8];
    #pragma unroll
    for (int kt = 0; kt < 8; ++kt)
        coffv[kt] = swz_chunk((uint32_t)(kt * 2) + lhi, rx) << 4;

    uint32_t A0[8][4], A1[8][4];
    {
        const uint32_t aBase0 = smem_b + HW_HI + (uint32_t)(warp_m * 32 + (lane & 15)) * 256u;
        const uint32_t aBase1 = aBase0 + 16u * 256u;
        #pragma unroll
        for (int kt = 0; kt < 8; ++kt) {
            ldsm_x4(A0[kt][0], A0[kt][1], A0[kt][2], A0[kt][3], aBase0 + coffv[kt]);
            ldsm_x4(A1[kt][0], A1[kt][1], A1[kt][2], A1[kt][3], aBase1 + coffv[kt]);
        }
    }

    // B row offsets: 2 n-halves x 2 n16 groups
    uint32_t bR[2][2];
    #pragma unroll
    for (int nh = 0; nh < 2; ++nh)
        #pragma unroll
        for (int g = 0; g < 2; ++g)
            bR[nh][g] = (uint32_t)(warp_n * 64 + nh * 32 + g * 16 + (lane & 15)) * 256u;

    const float* ht = (const float*)(smem + HT_OFF);
    const int quad = lane >> 2;
    const int hrow = warp_m * 32 + quad;

    float acc[2][8][4];
    #pragma unroll
    for (int mf = 0; mf < 2; ++mf)
        #pragma unroll
        for (int f = 0; f < 8; ++f)
            #pragma unroll
            for (int q = 0; q < 4; ++q) acc[mf][f][q] = 0.f;

    // -------- main loop --------
    int slot = 0, use = 0;
    for (int s = 0; s < NSTEPS; ++s) {
        const uint32_t par = (uint32_t)use & 1u;
        mbar_wait(smem_b + MB_FULL(slot), par);

        const float hA0 = ht[s * 128 + hrow];
        const float hB0 = ht[s * 128 + hrow + 8];
        const float hA1 = ht[s * 128 + hrow + 16];
        const float hB1 = ht[s * 128 + hrow + 24];
        const uint32_t bSlot = smem_b + W2_OFF + slot * STEP_BYTES;

        #pragma unroll
        for (int nh = 0; nh < 2; ++nh) {
            float d[8][4];
            #pragma unroll
            for (int kt = 0; kt < 8; ++kt) {
                uint32_t b0, b1r, b2, b3, c0, c1, c2, c3;
                ldsm_x4(b0, b1r, b2, b3, bSlot + bR[nh][0] + coffv[kt]);
                ldsm_x4(c0, c1, c2, c3, bSlot + bR[nh][1] + coffv[kt]);
                if (kt == 0) {
                    mma_zc(d[0], A0[0], b0, b2);  mma_zc(d[1], A0[0], b1r, b3);
                    mma_zc(d[2], A0[0], c0, c2);  mma_zc(d[3], A0[0], c1, c3);
                    mma_zc(d[4], A1[0], b0, b2);  mma_zc(d[5], A1[0], b1r, b3);
                    mma_zc(d[6], A1[0], c0, c2);  mma_zc(d[7], A1[0], c1, c3);
                } else {
                    mma_acc(d[0], A0[kt], b0, b2);  mma_acc(d[1], A0[kt], b1r, b3);
                    mma_acc(d[2], A0[kt], c0, c2);  mma_acc(d[3], A0[kt], c1, c3);
                    mma_acc(d[4], A1[kt], b0, b2);  mma_acc(d[5], A1[kt], b1r, b3);
                    mma_acc(d[6], A1[kt], c0, c2);  mma_acc(d[7], A1[kt], c1, c3);
                }
            }
            // scale into persistent accumulators (fp32)
            #pragma unroll
            for (int j = 0; j < 4; ++j) {
                float* a0 = acc[0][nh * 4 + j];
                float* a1 = acc[1][nh * 4 + j];
                a0[0] += hA0 * d[j][0];      a0[1] += hA0 * d[j][1];
                a0[2] += hB0 * d[j][2];      a0[3] += hB0 * d[j][3];
                a1[0] += hA1 * d[4 + j][0];  a1[1] += hA1 * d[4 + j][1];
                a1[2] += hB1 * d[4 + j][2];  a1[3] += hB1 * d[4 + j][3];
            }
        }
        __syncwarp();
        if (lane == 0) mbar_arrive(smem_b + MB_EMPTY(slot));

        if (tid == 0 && s + SLOTS < NSTEPS) {
            mbar_wait(smem_b + MB_EMPTY(slot), par);
            mbar_expect_tx(smem_b + MB_FULL(slot), STEP_BYTES);
            bulk_g2s(smem_b + W2_OFF + slot * STEP_BYTES,
                     g_w2h + (size_t)(s + SLOTS) * STEP_BYTES, STEP_BYTES,
                     smem_b + MB_FULL(slot));
        }
        if (++slot == SLOTS) { slot = 0; ++use; }
    }

    // -------- epilogue --------
    #pragma unroll
    for (int mf = 0; mf < 2; ++mf) {
        const int er = e0 + warp_m * 32 + mf * 16 + quad;
        #pragma unroll
        for (int gg = 0; gg < 4; ++gg)
            #pragma unroll
            for (int b = 0; b < 2; ++b) {
                const int f = gg * 2 + b;
                const int col = warp_n * 64 + gg * 16 + b * 8 + (lane & 3) * 2;
                *(float2*)(out + (size_t)er * DD + col) =
                    make_float2(acc[mf][f][0], acc[mf][f][1]);
                *(float2*)(out + (size_t)(er + 8) * DD + col) =
                    make_float2(acc[mf][f][2], acc[mf][f][3]);
            }
    }
}

// ---------------------------------------------------------------------------
// Tail: 16 edges/CTA, 256 threads, 8 warps m16n16 each (1M x 8N), A-resident.
// ---------------------------------------------------------------------------
__global__ void __launch_bounds__(256, 1)
edge_tail(const float* __restrict__ hw, const float* __restrict__ ef,
          const float* __restrict__ W1, const float* __restrict__ b1,
          float* __restrict__ out, int n, int e_base) {
    extern __shared__ __align__(1024) unsigned char smem[];
    const uint32_t smem_b = s2u(smem);
    const int tid = threadIdx.x;
    const int lane = tid & 31;
    const int wid = tid >> 5;        // 0..7 = n16 tile index
    const int e0 = e_base + blockIdx.x * 16;

    if (tid == 0) {
        #pragma unroll
        for (int i = 0; i < SLOTS; ++i) {
            mbar_init(smem_b + MB_FULL(i), 1);
            mbar_init(smem_b + MB_EMPTY(i), 8);
        }
        asm volatile("fence.mbarrier_init.release.cluster;" ::: "memory");
    }
    __syncthreads();
    if (tid == 0) {
        #pragma unroll
        for (int i = 0; i < SLOTS; ++i) {
            mbar_expect_tx(smem_b + MB_FULL(i), STEP_BYTES);
            bulk_g2s(smem_b + T_W2 + i * STEP_BYTES, g_w2h + (size_t)i * STEP_BYTES,
                     STEP_BYTES, smem_b + MB_FULL(i));
        }
    }

    {
        float* ef_s = (float*)(smem + T_EF);
        float* w1_s = (float*)(smem + T_W1);
        float* b1_s = (float*)(smem + T_B1);
        if (tid < 64) {
            int e = tid >> 2;
            float4 v = make_float4(0.f, 0.f, 0.f, 0.f);
            if (e0 + e < n) v = *(const float4*)(ef + (size_t)(e0 + e) * EDIM + (tid & 3) * 4);
            ((float4*)ef_s)[tid] = v;
        }
        ((float4*)w1_s)[tid] = ((const float4*)W1)[tid];
        ((float4*)w1_s)[tid + 256] = ((const float4*)W1)[tid + 256];
        if (tid < EH) b1_s[tid] = b1[tid];
    }
    __syncthreads();

    {
        const float* ef_s = (const float*)(smem + T_EF);
        const float* w1_s = (const float*)(smem + T_W1);
        const float* b1_s = (const float*)(smem + T_B1);
        float* ht = (float*)(smem + T_HT);
        const int e = tid >> 4;          // 0..15
        const int part = tid & 15;       // 8 h each
        float efr[EDIM];
        #pragma unroll
        for (int k = 0; k < EDIM; ++k) efr[k] = ef_s[e * EDIM + k];
        const int h0 = part * 8;
        #pragma unroll
        for (int hh = 0; hh < 8; hh += 4) {
            float4 acc4 = *(const float4*)(b1_s + h0 + hh);
            #pragma unroll
            for (int k = 0; k < EDIM; ++k) {
                float4 w = *(const float4*)(w1_s + k * EH + h0 + hh);
                acc4.x += efr[k] * w.x; acc4.y += efr[k] * w.y;
                acc4.z += efr[k] * w.z; acc4.w += efr[k] * w.w;
            }
            ht[(h0 + hh + 0) * 16 + e] = fmaxf(acc4.x, 0.f);
            ht[(h0 + hh + 1) * 16 + e] = fmaxf(acc4.y, 0.f);
            ht[(h0 + hh + 2) * 16 + e] = fmaxf(acc4.z, 0.f);
            ht[(h0 + hh + 3) * 16 + e] = fmaxf(acc4.w, 0.f);
        }
        if (part == 0) ht[128 * 16 + e] = 1.0f;
    }
    __syncthreads();

    {
        int r = tid >> 4;               // 0..15
        int c = tid & 15;
        float4 a = make_float4(0.f, 0.f, 0.f, 0.f), b = a;
        if (e0 + r < n) {
            const float* s = hw + (size_t)(e0 + r) * DD + c * 8;
            a = *(const float4*)s;
            b = *(const float4*)(s + 4);
        }
        __half2 h0 = __floats2half2_rn(a.x, a.y);
        __half2 h1 = __floats2half2_rn(a.z, a.w);
        __half2 h2 = __floats2half2_rn(b.x, b.y);
        __half2 h3 = __floats2half2_rn(b.z, b.w);
        uint32_t off = (uint32_t)r * 256u + (swz_chunk((uint32_t)c, (uint32_t)(r & 7)) << 4);
        uint4 v;
        v.x = *(uint32_t*)&h0; v.y = *(uint32_t*)&h1;
        v.z = *(uint32_t*)&h2; v.w = *(uint32_t*)&h3;
        *(uint4*)(smem + T_HW + off) = v;
    }
    __syncthreads();

    const uint32_t rx = (uint32_t)(lane & 7);
    const uint32_t lhi = (uint32_t)(lane >> 4);
    uint32_t coffv[8];
    #pragma unroll
    for (int kt = 0; kt < 8; ++kt)
        coffv[kt] = swz_chunk((uint32_t)(kt * 2) + lhi, rx) << 4;

    uint32_t A[8][4];
    {
        const uint32_t aBase = smem_b + T_HW + (uint32_t)(lane & 15) * 256u;
        #pragma unroll
        for (int kt = 0; kt < 8; ++kt)
            ldsm_x4(A[kt][0], A[kt][1], A[kt][2], A[kt][3], aBase + coffv[kt]);
    }
    const uint32_t bRow = (uint32_t)(wid * 16 + (lane & 15)) * 256u;
    const float* ht = (const float*)(smem + T_HT);
    const int quad = lane >> 2;

    float acc[2][4];
    #pragma unroll
    for (int f = 0; f < 2; ++f)
        #pragma unroll
        for (int q = 0; q < 4; ++q) acc[f][q] = 0.f;

    int slot = 0, use = 0;
    for (int s = 0; s < NSTEPS; ++s) {
        const uint32_t par = (uint32_t)use & 1u;
        mbar_wait(smem_b + MB_FULL(slot), par);

        const float hA = ht[s * 16 + quad];
        const float hB = ht[s * 16 + quad + 8];
        const uint32_t bSlot = smem_b + T_W2 + slot * STEP_BYTES;

        float d[2][4];
        #pragma unroll
        for (int kt = 0; kt < 8; ++kt) {
            uint32_t b0, b1r, b2, b3;
            ldsm_x4(b0, b1r, b2, b3, bSlot + bRow + coffv[kt]);
            if (kt == 0) {
                mma_zc(d[0], A[0], b0, b2);
                mma_zc(d[1], A[0], b1r, b3);
            } else {
                mma_acc(d[0], A[kt], b0, b2);
                mma_acc(d[1], A[kt], b1r, b3);
            }
        }
        __syncwarp();
        if (lane == 0) mbar_arrive(smem_b + MB_EMPTY(slot));

        #pragma unroll
        for (int f = 0; f < 2; ++f) {
            acc[f][0] += hA * d[f][0];  acc[f][1] += hA * d[f][1];
            acc[f][2] += hB * d[f][2];  acc[f][3] += hB * d[f][3];
        }

        if (tid == 0 && s + SLOTS < NSTEPS) {
            mbar_wait(smem_b + MB_EMPTY(slot), par);
            mbar_expect_tx(smem_b + MB_FULL(slot), STEP_BYTES);
            bulk_g2s(smem_b + T_W2 + slot * STEP_BYTES,
                     g_w2h + (size_t)(s + SLOTS) * STEP_BYTES, STEP_BYTES,
                     smem_b + MB_FULL(slot));
        }
        if (++slot == SLOTS) { slot = 0; ++use; }
    }

    const int er = e0 + quad;
    #pragma unroll
    for (int b = 0; b < 2; ++b) {
        const int col = wid * 16 + b * 8 + (lane & 3) * 2;
        if (er < n)
            *(float2*)(out + (size_t)er * DD + col) = make_float2(acc[b][0], acc[b][1]);
        if (er + 8 < n)
            *(float2*)(out + (size_t)(er + 8) * DD + col) = make_float2(acc[b][2], acc[b][3]);
    }
}

// ---------------------------------------------------------------------------
extern "C" void kernel_launch(void* const* d_in, const int* in_sizes, int n_in,
                              void* d_out, int out_size) {
    const float* hw = (const float*)d_in[1];
    const float* ef = (const float*)d_in[2];
    const float* W1 = (const float*)d_in[3];
    const float* b1 = (const float*)d_in[4];
    const float* W2 = (const float*)d_in[5];
    const float* b2 = (const float*)d_in[6];
    const int n = in_sizes[1] / DD;

    w2_prepass<<<NSTEPS, 256>>>(W2, b2);

    int full = n / 128;
    if (full > 148) full = 148;
    const int rem = n - full * 128;
    const int jobs = (rem + 15) / 16;
    if (jobs > 0) {
        cudaFuncSetAttribute(edge_tail, cudaFuncAttributeMaxDynamicSharedMemorySize,
                             TAIL_SMEM);
        edge_tail<<<jobs, 256, TAIL_SMEM>>>(hw, ef, W1, b1, (float*)d_out, n, full * 128);
    }
    if (full > 0) {
        cudaFuncSetAttribute(edge_main, cudaFuncAttributeMaxDynamicSharedMemorySize,
                             SMEM_TOTAL);
        edge_main<<<full, 256, SMEM_TOTAL>>>(hw, ef, W1, b1, (float*)d_out, n);
    }
}

// round 8
// speedup vs baseline: 1.8675x; 1.0032x over previous
#include <cuda_runtime.h>
#include <cuda_fp16.h>
#include <stdint.h>

// ---------------------------------------------------------------------------
// EdgeNetwork: messages_e = sum_h H[e,h]*(hw_e @ W2[h]^T) + (hw_e @ b2-tile)
// H applied POST-MMA in fp32. A (= hw) fragments register-resident.
// Main: 148 CTAs x 128 edges, 256 threads, 8 warps m32n64, ONE full pass
// (d[16][4] -> 16 independent HMMA chains/warp for ILP).
// Tail: 66 jobs x 16 edges, 256 threads, 8 warps m16n16, 4 W2 slots.
// W2 fp16 image (prepass) streamed via cp.async.bulk.
// ---------------------------------------------------------------------------

#define DD        128
#define EDIM      16
#define EH        128
#define NSTEPS    129
#define STEP_BYTES 32768
#define SLOTS     3
#define TSLOTS    4

// ---- main smem layout ----
#define MB_FULL(i)  ((i)*8)
#define MB_EMPTY(i) (32 + (i)*8)
#define HW_HI       1024                 // 128 x 256B = 32768
#define HT_OFF      33792                // 129*128*4 = 66048 -> ends 99840
#define W2_OFF      100352               // 3 x 32768 -> ends 198656
#define SMEM_TOTAL  198656
#define SCR_EF      1024
#define SCR_W1      9216
#define SCR_B1      17408

// ---- tail smem layout ----
#define T_HW       1024                  // 16 x 256B = 4096
#define T_HT       5120                  // 129*16*4 = 8256 -> 13376
#define T_W2       13824                 // 4 x 32768 -> 144896
#define T_EF       144896
#define T_W1       145920
#define T_B1       154112
#define TAIL_SMEM  154624

static __device__ __align__(128) unsigned char g_w2h[(size_t)NSTEPS * STEP_BYTES];

__device__ __forceinline__ uint32_t s2u(const void* p) {
    return (uint32_t)__cvta_generic_to_shared(p);
}
__device__ __forceinline__ uint32_t swz_chunk(uint32_t c, uint32_t r7) {
    return (c & 8u) | ((c & 7u) ^ r7);
}
__device__ __forceinline__ void mbar_init(uint32_t a, uint32_t cnt) {
    asm volatile("mbarrier.init.shared.b64 [%0], %1;" :: "r"(a), "r"(cnt) : "memory");
}
__device__ __forceinline__ void mbar_expect_tx(uint32_t a, uint32_t bytes) {
    asm volatile("mbarrier.arrive.expect_tx.shared.b64 _, [%0], %1;"
                 :: "r"(a), "r"(bytes) : "memory");
}
__device__ __forceinline__ void mbar_arrive(uint32_t a) {
    asm volatile("mbarrier.arrive.shared.b64 _, [%0];" :: "r"(a) : "memory");
}
__device__ __forceinline__ void mbar_wait(uint32_t a, uint32_t parity) {
    asm volatile(
        "{\n\t.reg .pred P;\n\t"
        "W_%=:\n\t"
        "mbarrier.try_wait.parity.shared.b64 P, [%0], %1;\n\t"
        "@P bra.uni D_%=;\n\t"
        "bra.uni W_%=;\n\t"
        "D_%=:\n\t}"
        :: "r"(a), "r"(parity) : "memory");
}
__device__ __forceinline__ void bulk_g2s(uint32_t dst, const void* src, uint32_t bytes,
                                         uint32_t mbar) {
    asm volatile(
        "cp.async.bulk.shared::cluster.global.mbarrier::complete_tx::bytes [%0], [%1], %2, [%3];"
        :: "r"(dst), "l"(src), "r"(bytes), "r"(mbar) : "memory");
}
__device__ __forceinline__ void ldsm_x4(uint32_t& r0, uint32_t& r1, uint32_t& r2, uint32_t& r3,
                                        uint32_t addr) {
    asm volatile("ldmatrix.sync.aligned.m8n8.x4.shared.b16 {%0,%1,%2,%3}, [%4];"
                 : "=r"(r0), "=r"(r1), "=r"(r2), "=r"(r3) : "r"(addr));
}
__device__ __forceinline__ void mma_acc(float* c, const uint32_t* a,
                                        uint32_t b0, uint32_t b1) {
    asm volatile(
        "mma.sync.aligned.m16n8k16.row.col.f32.f16.f16.f32 "
        "{%0,%1,%2,%3}, {%4,%5,%6,%7}, {%8,%9}, {%0,%1,%2,%3};"
        : "+f"(c[0]), "+f"(c[1]), "+f"(c[2]), "+f"(c[3])
        : "r"(a[0]), "r"(a[1]), "r"(a[2]), "r"(a[3]), "r"(b0), "r"(b1));
}
__device__ __forceinline__ void mma_zc(float* d, const uint32_t* a,
                                       uint32_t b0, uint32_t b1) {
    asm volatile(
        "mma.sync.aligned.m16n8k16.row.col.f32.f16.f16.f32 "
        "{%0,%1,%2,%3}, {%4,%5,%6,%7}, {%8,%9}, {%10,%11,%12,%13};"
        : "=f"(d[0]), "=f"(d[1]), "=f"(d[2]), "=f"(d[3])
        : "r"(a[0]), "r"(a[1]), "r"(a[2]), "r"(a[3]), "r"(b0), "r"(b1),
          "f"(0.f), "f"(0.f), "f"(0.f), "f"(0.f));
}

// ---------------------------------------------------------------------------
__global__ void __launch_bounds__(256) w2_prepass(const float* __restrict__ W2,
                                                  const float* __restrict__ b2) {
    const int h = blockIdx.x;
    const int tid = threadIdx.x;
    const float* src = (h < EH) ? (W2 + (size_t)h * (DD * DD)) : b2;
    unsigned char* dst = g_w2h + (size_t)h * STEP_BYTES;
    #pragma unroll
    for (int it = 0; it < 8; ++it) {
        int cid = tid + it * 256;
        int i = cid >> 4;
        int c = cid & 15;
        const float* s = src + (size_t)i * DD + c * 8;
        float4 a = *(const float4*)s;
        float4 b = *(const float4*)(s + 4);
        __half2 h0 = __floats2half2_rn(a.x, a.y);
        __half2 h1 = __floats2half2_rn(a.z, a.w);
        __half2 h2 = __floats2half2_rn(b.x, b.y);
        __half2 h3 = __floats2half2_rn(b.z, b.w);
        uint32_t off = (uint32_t)i * 256u + (swz_chunk((uint32_t)c, (uint32_t)(i & 7)) << 4);
        uint4 v;
        v.x = *(uint32_t*)&h0; v.y = *(uint32_t*)&h1;
        v.z = *(uint32_t*)&h2; v.w = *(uint32_t*)&h3;
        *(uint4*)(dst + off) = v;
    }
}

// ---------------------------------------------------------------------------
// Main: 128 edges/CTA, 256 threads, 8 warps 4(M)x2(N) -> m32 x n64,
// A register-resident, single full-width pass (16 chains).
// ---------------------------------------------------------------------------
__global__ void __launch_bounds__(256, 1)
edge_main(const float* __restrict__ hw, const float* __restrict__ ef,
          const float* __restrict__ W1, const float* __restrict__ b1,
          float* __restrict__ out, int n) {
    extern __shared__ __align__(1024) unsigned char smem[];
    const uint32_t smem_b = s2u(smem);
    const int tid = threadIdx.x;
    const int lane = tid & 31;
    const int wid = tid >> 5;
    const int warp_m = wid & 3;
    const int warp_n = wid >> 2;       // 0..1
    const int e0 = blockIdx.x * 128;

    if (tid == 0) {
        #pragma unroll
        for (int i = 0; i < SLOTS; ++i) {
            mbar_init(smem_b + MB_FULL(i), 1);
            mbar_init(smem_b + MB_EMPTY(i), 8);
        }
        asm volatile("fence.mbarrier_init.release.cluster;" ::: "memory");
    }
    __syncthreads();
    if (tid == 0) {
        #pragma unroll
        for (int i = 0; i < SLOTS; ++i) {
            mbar_expect_tx(smem_b + MB_FULL(i), STEP_BYTES);
            bulk_g2s(smem_b + W2_OFF + i * STEP_BYTES, g_w2h + (size_t)i * STEP_BYTES,
                     STEP_BYTES, smem_b + MB_FULL(i));
        }
    }

    // -------- stage ef / W1 / b1 --------
    {
        float* ef_s = (float*)(smem + SCR_EF);
        float* w1_s = (float*)(smem + SCR_W1);
        float* b1_s = (float*)(smem + SCR_B1);
        ((float4*)ef_s)[tid] = ((const float4*)(ef + (size_t)e0 * EDIM))[tid];
        ((float4*)ef_s)[tid + 256] = ((const float4*)(ef + (size_t)e0 * EDIM))[tid + 256];
        ((float4*)w1_s)[tid] = ((const float4*)W1)[tid];
        ((float4*)w1_s)[tid + 256] = ((const float4*)W1)[tid + 256];
        if (tid < EH) b1_s[tid] = b1[tid];
    }
    __syncthreads();

    // -------- MLP: Ht[h][e] fp32, step 128 = 1.0 --------
    {
        const float* ef_s = (const float*)(smem + SCR_EF);
        const float* w1_s = (const float*)(smem + SCR_W1);
        const float* b1_s = (const float*)(smem + SCR_B1);
        float* ht = (float*)(smem + HT_OFF);
        const int e = tid >> 1;
        const int part = tid & 1;
        float efr[EDIM];
        #pragma unroll
        for (int k = 0; k < EDIM; ++k) efr[k] = ef_s[e * EDIM + k];
        const int h0 = part * 64;
        #pragma unroll 4
        for (int hh = 0; hh < 64; hh += 4) {
            float4 acc4 = *(const float4*)(b1_s + h0 + hh);
            #pragma unroll
            for (int k = 0; k < EDIM; ++k) {
                float4 w = *(const float4*)(w1_s + k * EH + h0 + hh);
                acc4.x += efr[k] * w.x; acc4.y += efr[k] * w.y;
                acc4.z += efr[k] * w.z; acc4.w += efr[k] * w.w;
            }
            ht[(h0 + hh + 0) * 128 + e] = fmaxf(acc4.x, 0.f);
            ht[(h0 + hh + 1) * 128 + e] = fmaxf(acc4.y, 0.f);
            ht[(h0 + hh + 2) * 128 + e] = fmaxf(acc4.z, 0.f);
            ht[(h0 + hh + 3) * 128 + e] = fmaxf(acc4.w, 0.f);
        }
        if (part == 0) ht[128 * 128 + e] = 1.0f;
    }
    __syncthreads();

    // -------- hw fp16 image --------
    {
        #pragma unroll
        for (int q = 0; q < 8; ++q) {
            int cid = tid + q * 256;
            int r = cid >> 4;
            int c = cid & 15;
            const float* s = hw + (size_t)(e0 + r) * DD + c * 8;
            float4 a = *(const float4*)s;
            float4 b = *(const float4*)(s + 4);
            __half2 h0 = __floats2half2_rn(a.x, a.y);
            __half2 h1 = __floats2half2_rn(a.z, a.w);
            __half2 h2 = __floats2half2_rn(b.x, b.y);
            __half2 h3 = __floats2half2_rn(b.z, b.w);
            uint32_t off = (uint32_t)r * 256u + (swz_chunk((uint32_t)c, (uint32_t)(r & 7)) << 4);
            uint4 v;
            v.x = *(uint32_t*)&h0; v.y = *(uint32_t*)&h1;
            v.z = *(uint32_t*)&h2; v.w = *(uint32_t*)&h3;
            *(uint4*)(smem + HW_HI + off) = v;
        }
    }
    __syncthreads();

    // -------- A fragments into registers (step-invariant) --------
    const uint32_t rx = (uint32_t)(lane & 7);
    const uint32_t lhi = (uint32_t)(lane >> 4);
    uint32_t coffv[8];
    #pragma unroll
    for (int kt = 0; kt < 8; ++kt)
        coffv[kt] = swz_chunk((uint32_t)(kt * 2) + lhi, rx) << 4;

    uint32_t A0[8][4], A1[8][4];
    {
        const uint32_t aBase0 = smem_b + HW_HI + (uint32_t)(warp_m * 32 + (lane & 15)) * 256u;
        const uint32_t aBase1 = aBase0 + 16u * 256u;
        #pragma unroll
        for (int kt = 0; kt < 8; ++kt) {
            ldsm_x4(A0[kt][0], A0[kt][1], A0[kt][2], A0[kt][3], aBase0 + coffv[kt]);
            ldsm_x4(A1[kt][0], A1[kt][1], A1[kt][2], A1[kt][3], aBase1 + coffv[kt]);
        }
    }

    // B row offsets: 4 n16 groups spanning this warp's n64
    uint32_t bR[4];
    #pragma unroll
    for (int g = 0; g < 4; ++g)
        bR[g] = (uint32_t)(warp_n * 64 + g * 16 + (lane & 15)) * 256u;

    const float* ht = (const float*)(smem + HT_OFF);
    const int quad = lane >> 2;
    const int hrow = warp_m * 32 + quad;

    float acc[2][8][4];
    #pragma unroll
    for (int mf = 0; mf < 2; ++mf)
        #pragma unroll
        for (int f = 0; f < 8; ++f)
            #pragma unroll
            for (int q = 0; q < 4; ++q) acc[mf][f][q] = 0.f;

    // -------- main loop --------
    int slot = 0, use = 0;
    for (int s = 0; s < NSTEPS; ++s) {
        const uint32_t par = (uint32_t)use & 1u;
        mbar_wait(smem_b + MB_FULL(slot), par);

        const float hA0 = ht[s * 128 + hrow];
        const float hB0 = ht[s * 128 + hrow + 8];
        const float hA1 = ht[s * 128 + hrow + 16];
        const float hB1 = ht[s * 128 + hrow + 24];
        const uint32_t bSlot = smem_b + W2_OFF + slot * STEP_BYTES;

        float d[16][4];   // 16 independent chains: [mf*8 + g*2 + b]
        #pragma unroll
        for (int kt = 0; kt < 8; ++kt) {
            #pragma unroll
            for (int g = 0; g < 4; ++g) {
                uint32_t b0, b1r, b2, b3;
                ldsm_x4(b0, b1r, b2, b3, bSlot + bR[g] + coffv[kt]);
                if (kt == 0) {
                    mma_zc(d[g * 2 + 0], A0[0], b0, b2);
                    mma_zc(d[g * 2 + 1], A0[0], b1r, b3);
                    mma_zc(d[8 + g * 2 + 0], A1[0], b0, b2);
                    mma_zc(d[8 + g * 2 + 1], A1[0], b1r, b3);
                } else {
                    mma_acc(d[g * 2 + 0], A0[kt], b0, b2);
                    mma_acc(d[g * 2 + 1], A0[kt], b1r, b3);
                    mma_acc(d[8 + g * 2 + 0], A1[kt], b0, b2);
                    mma_acc(d[8 + g * 2 + 1], A1[kt], b1r, b3);
                }
            }
        }
        __syncwarp();
        if (lane == 0) mbar_arrive(smem_b + MB_EMPTY(slot));

        #pragma unroll
        for (int j = 0; j < 8; ++j) {
            float* a0 = acc[0][j];
            float* a1 = acc[1][j];
            a0[0] += hA0 * d[j][0];      a0[1] += hA0 * d[j][1];
            a0[2] += hB0 * d[j][2];      a0[3] += hB0 * d[j][3];
            a1[0] += hA1 * d[8 + j][0];  a1[1] += hA1 * d[8 + j][1];
            a1[2] += hB1 * d[8 + j][2];  a1[3] += hB1 * d[8 + j][3];
        }

        if (tid == 0 && s + SLOTS < NSTEPS) {
            mbar_wait(smem_b + MB_EMPTY(slot), par);
            mbar_expect_tx(smem_b + MB_FULL(slot), STEP_BYTES);
            bulk_g2s(smem_b + W2_OFF + slot * STEP_BYTES,
                     g_w2h + (size_t)(s + SLOTS) * STEP_BYTES, STEP_BYTES,
                     smem_b + MB_FULL(slot));
        }
        if (++slot == SLOTS) { slot = 0; ++use; }
    }

    // -------- epilogue --------
    #pragma unroll
    for (int mf = 0; mf < 2; ++mf) {
        const int er = e0 + warp_m * 32 + mf * 16 + quad;
        #pragma unroll
        for (int gg = 0; gg < 4; ++gg)
            #pragma unroll
            for (int b = 0; b < 2; ++b) {
                const int f = gg * 2 + b;
                const int col = warp_n * 64 + gg * 16 + b * 8 + (lane & 3) * 2;
                *(float2*)(out + (size_t)er * DD + col) =
                    make_float2(acc[mf][f][0], acc[mf][f][1]);
                *(float2*)(out + (size_t)(er + 8) * DD + col) =
                    make_float2(acc[mf][f][2], acc[mf][f][3]);
            }
    }
}

// ---------------------------------------------------------------------------
// Tail: 16 edges/CTA, 256 threads, 8 warps m16n16, A-resident, 4 slots.
// ---------------------------------------------------------------------------
__global__ void __launch_bounds__(256, 1)
edge_tail(const float* __restrict__ hw, const float* __restrict__ ef,
          const float* __restrict__ W1, const float* __restrict__ b1,
          float* __restrict__ out, int n, int e_base) {
    extern __shared__ __align__(1024) unsigned char smem[];
    const uint32_t smem_b = s2u(smem);
    const int tid = threadIdx.x;
    const int lane = tid & 31;
    const int wid = tid >> 5;
    const int e0 = e_base + blockIdx.x * 16;

    if (tid == 0) {
        #pragma unroll
        for (int i = 0; i < TSLOTS; ++i) {
            mbar_init(smem_b + MB_FULL(i), 1);
            mbar_init(smem_b + MB_EMPTY(i), 8);
        }
        asm volatile("fence.mbarrier_init.release.cluster;" ::: "memory");
    }
    __syncthreads();
    if (tid == 0) {
        #pragma unroll
        for (int i = 0; i < TSLOTS; ++i) {
            mbar_expect_tx(smem_b + MB_FULL(i), STEP_BYTES);
            bulk_g2s(smem_b + T_W2 + i * STEP_BYTES, g_w2h + (size_t)i * STEP_BYTES,
                     STEP_BYTES, smem_b + MB_FULL(i));
        }
    }

    {
        float* ef_s = (float*)(smem + T_EF);
        float* w1_s = (float*)(smem + T_W1);
        float* b1_s = (float*)(smem + T_B1);
        if (tid < 64) {
            int e = tid >> 2;
            float4 v = make_float4(0.f, 0.f, 0.f, 0.f);
            if (e0 + e < n) v = *(const float4*)(ef + (size_t)(e0 + e) * EDIM + (tid & 3) * 4);
            ((float4*)ef_s)[tid] = v;
        }
        ((float4*)w1_s)[tid] = ((const float4*)W1)[tid];
        ((float4*)w1_s)[tid + 256] = ((const float4*)W1)[tid + 256];
        if (tid < EH) b1_s[tid] = b1[tid];
    }
    __syncthreads();

    {
        const float* ef_s = (const float*)(smem + T_EF);
        const float* w1_s = (const float*)(smem + T_W1);
        const float* b1_s = (const float*)(smem + T_B1);
        float* ht = (float*)(smem + T_HT);
        const int e = tid >> 4;
        const int part = tid & 15;
        float efr[EDIM];
        #pragma unroll
        for (int k = 0; k < EDIM; ++k) efr[k] = ef_s[e * EDIM + k];
        const int h0 = part * 8;
        #pragma unroll
        for (int hh = 0; hh < 8; hh += 4) {
            float4 acc4 = *(const float4*)(b1_s + h0 + hh);
            #pragma unroll
            for (int k = 0; k < EDIM; ++k) {
                float4 w = *(const float4*)(w1_s + k * EH + h0 + hh);
                acc4.x += efr[k] * w.x; acc4.y += efr[k] * w.y;
                acc4.z += efr[k] * w.z; acc4.w += efr[k] * w.w;
            }
            ht[(h0 + hh + 0) * 16 + e] = fmaxf(acc4.x, 0.f);
            ht[(h0 + hh + 1) * 16 + e] = fmaxf(acc4.y, 0.f);
            ht[(h0 + hh + 2) * 16 + e] = fmaxf(acc4.z, 0.f);
            ht[(h0 + hh + 3) * 16 + e] = fmaxf(acc4.w, 0.f);
        }
        if (part == 0) ht[128 * 16 + e] = 1.0f;
    }
    __syncthreads();

    {
        int r = tid >> 4;
        int c = tid & 15;
        float4 a = make_float4(0.f, 0.f, 0.f, 0.f), b = a;
        if (e0 + r < n) {
            const float* s = hw + (size_t)(e0 + r) * DD + c * 8;
            a = *(const float4*)s;
            b = *(const float4*)(s + 4);
        }
        __half2 h0 = __floats2half2_rn(a.x, a.y);
        __half2 h1 = __floats2half2_rn(a.z, a.w);
        __half2 h2 = __floats2half2_rn(b.x, b.y);
        __half2 h3 = __floats2half2_rn(b.z, b.w);
        uint32_t off = (uint32_t)r * 256u + (swz_chunk((uint32_t)c, (uint32_t)(r & 7)) << 4);
        uint4 v;
        v.x = *(uint32_t*)&h0; v.y = *(uint32_t*)&h1;
        v.z = *(uint32_t*)&h2; v.w = *(uint32_t*)&h3;
        *(uint4*)(smem + T_HW + off) = v;
    }
    __syncthreads();

    const uint32_t rx = (uint32_t)(lane & 7);
    const uint32_t lhi = (uint32_t)(lane >> 4);
    uint32_t coffv[8];
    #pragma unroll
    for (int kt = 0; kt < 8; ++kt)
        coffv[kt] = swz_chunk((uint32_t)(kt * 2) + lhi, rx) << 4;

    uint32_t A[8][4];
    {
        const uint32_t aBase = smem_b + T_HW + (uint32_t)(lane & 15) * 256u;
        #pragma unroll
        for (int kt = 0; kt < 8; ++kt)
            ldsm_x4(A[kt][0], A[kt][1], A[kt][2], A[kt][3], aBase + coffv[kt]);
    }
    const uint32_t bRow = (uint32_t)(wid * 16 + (lane & 15)) * 256u;
    const float* ht = (const float*)(smem + T_HT);
    const int quad = lane >> 2;

    float acc[2][4];
    #pragma unroll
    for (int f = 0; f < 2; ++f)
        #pragma unroll
        for (int q = 0; q < 4; ++q) acc[f][q] = 0.f;

    int slot = 0, use = 0;
    for (int s = 0; s < NSTEPS; ++s) {
        const uint32_t par = (uint32_t)use & 1u;
        mbar_wait(smem_b + MB_FULL(slot), par);

        const float hA = ht[s * 16 + quad];
        const float hB = ht[s * 16 + quad + 8];
        const uint32_t bSlot = smem_b + T_W2 + slot * STEP_BYTES;

        float d[2][4];
        #pragma unroll
        for (int kt = 0; kt < 8; ++kt) {
            uint32_t b0, b1r, b2, b3;
            ldsm_x4(b0, b1r, b2, b3, bSlot + bRow + coffv[kt]);
            if (kt == 0) {
                mma_zc(d[0], A[0], b0, b2);
                mma_zc(d[1], A[0], b1r, b3);
            } else {
                mma_acc(d[0], A[kt], b0, b2);
                mma_acc(d[1], A[kt], b1r, b3);
            }
        }
        __syncwarp();
        if (lane == 0) mbar_arrive(smem_b + MB_EMPTY(slot));

        #pragma unroll
        for (int f = 0; f < 2; ++f) {
            acc[f][0] += hA * d[f][0];  acc[f][1] += hA * d[f][1];
            acc[f][2] += hB * d[f][2];  acc[f][3] += hB * d[f][3];
        }

        if (tid == 0 && s + TSLOTS < NSTEPS) {
            mbar_wait(smem_b + MB_EMPTY(slot), par);
            mbar_expect_tx(smem_b + MB_FULL(slot), STEP_BYTES);
            bulk_g2s(smem_b + T_W2 + slot * STEP_BYTES,
                     g_w2h + (size_t)(s + TSLOTS) * STEP_BYTES, STEP_BYTES,
                     smem_b + MB_FULL(slot));
        }
        if (++slot == TSLOTS) { slot = 0; ++use; }
    }

    const int er = e0 + quad;
    #pragma unroll
    for (int b = 0; b < 2; ++b) {
        const int col = wid * 16 + b * 8 + (lane & 3) * 2;
        if (er < n)
            *(float2*)(out + (size_t)er * DD + col) = make_float2(acc[b][0], acc[b][1]);
        if (er + 8 < n)
            *(float2*)(out + (size_t)(er + 8) * DD + col) = make_float2(acc[b][2], acc[b][3]);
    }
}

// ---------------------------------------------------------------------------
extern "C" void kernel_launch(void* const* d_in, const int* in_sizes, int n_in,
                              void* d_out, int out_size) {
    const float* hw = (const float*)d_in[1];
    const float* ef = (const float*)d_in[2];
    const float* W1 = (const float*)d_in[3];
    const float* b1 = (const float*)d_in[4];
    const float* W2 = (const float*)d_in[5];
    const float* b2 = (const float*)d_in[6];
    const int n = in_sizes[1] / DD;

    w2_prepass<<<NSTEPS, 256>>>(W2, b2);

    int full = n / 128;
    if (full > 148) full = 148;
    const int rem = n - full * 128;
    const int jobs = (rem + 15) / 16;
    if (jobs > 0) {
        cudaFuncSetAttribute(edge_tail, cudaFuncAttributeMaxDynamicSharedMemorySize,
                             TAIL_SMEM);
        edge_tail<<<jobs, 256, TAIL_SMEM>>>(hw, ef, W1, b1, (float*)d_out, n, full * 128);
    }
    if (full > 0) {
        cudaFuncSetAttribute(edge_main, cudaFuncAttributeMaxDynamicSharedMemorySize,
                             SMEM_TOTAL);
        edge_main<<<full, 256, SMEM_TOTAL>>>(hw, ef, W1, b1, (float*)d_out, n);
    }
}